// round 15
// baseline (speedup 1.0000x reference)
#include <cuda_runtime.h>
#include <cuda_bf16.h>
#include <cstdint>

#define BSZ   4
#define TOTAL 2064
#define DM    1024
#define NSN   16
#define OUTN  256
#define QLEN  272
#define NH    16
#define HD    64
#define FFND  4096
#define MAXS  2048

// Scratch (static device globals; no allocation allowed)
__device__ float g_xn  [BSZ*TOTAL*DM];
__device__ float g_q   [BSZ*QLEN*DM];
__device__ float g_kv  [BSZ*TOTAL*2*DM];
__device__ float g_attn[BSZ*QLEN*DM];
__device__ float g_h1  [BSZ*QLEN*DM];
__device__ float g_hn  [BSZ*QLEN*DM];
__device__ float g_tns [BSZ*NSN*FFND];
__device__ float g_fns [BSZ*NSN*DM];
__device__ float g_part[4*1024*1024];
// bf16 activations + transposed bf16 weights ([N,K] row-major)
__device__ __nv_bfloat16 g_xnb [BSZ*TOTAL*DM];
__device__ __nv_bfloat16 g_hnb [BSZ*QLEN*DM];
__device__ __nv_bfloat16 g_tsb [BSZ*OUTN*FFND];
__device__ __nv_bfloat16 g_wqkvb[3*DM*DM];
__device__ __nv_bfloat16 g_w1b  [FFND*DM];
__device__ __nv_bfloat16 g_w2b  [DM*FFND];

__device__ __forceinline__ float rtf32(float x) {
    uint32_t u;
    asm("cvt.rna.tf32.f32 %0, %1;" : "=r"(u) : "f"(x));
    return __uint_as_float(u);
}
__device__ __forceinline__ uint32_t f2u(float x) { return __float_as_uint(x); }

__device__ __forceinline__ void cpa16(uint32_t dst, const void* src) {
    asm volatile("cp.async.ca.shared.global [%0], [%1], 16;" :: "r"(dst), "l"(src));
}

__device__ __forceinline__ void mma_tf32(float* c,
        uint32_t a0, uint32_t a1, uint32_t a2, uint32_t a3,
        uint32_t b0, uint32_t b1) {
    asm volatile(
        "mma.sync.aligned.m16n8k8.row.col.f32.tf32.tf32.f32 "
        "{%0,%1,%2,%3}, {%4,%5,%6,%7}, {%8,%9}, {%0,%1,%2,%3};\n"
        : "+f"(c[0]), "+f"(c[1]), "+f"(c[2]), "+f"(c[3])
        : "r"(a0), "r"(a1), "r"(a2), "r"(a3), "r"(b0), "r"(b1));
}
__device__ __forceinline__ void mma_bf16(float* c,
        uint32_t a0, uint32_t a1, uint32_t a2, uint32_t a3,
        uint32_t b0, uint32_t b1) {
    asm volatile(
        "mma.sync.aligned.m16n8k16.row.col.f32.bf16.bf16.f32 "
        "{%0,%1,%2,%3}, {%4,%5,%6,%7}, {%8,%9}, {%0,%1,%2,%3};\n"
        : "+f"(c[0]), "+f"(c[1]), "+f"(c[2]), "+f"(c[3])
        : "r"(a0), "r"(a1), "r"(a2), "r"(a3), "r"(b0), "r"(b1));
}

__device__ __forceinline__ void ldsm4(uint32_t* r, uint32_t addr) {
    asm volatile("ldmatrix.sync.aligned.m8n8.x4.shared.b16 {%0,%1,%2,%3}, [%4];"
        : "=r"(r[0]), "=r"(r[1]), "=r"(r[2]), "=r"(r[3]) : "r"(addr));
}

// ---------------- transpose + bf16 convert ----------------
__global__ __launch_bounds__(256) void transpose_bf16_kernel(const float* __restrict__ in,
        __nv_bfloat16* __restrict__ out, int R, int C) {
    __shared__ float tile[32][33];
    int c0 = blockIdx.x*32, r0 = blockIdx.y*32;
    int tx = threadIdx.x, ty = threadIdx.y;
    for (int i = ty; i < 32; i += 8)
        tile[i][tx] = in[(long)(r0+i)*C + c0 + tx];
    __syncthreads();
    for (int i = ty; i < 32; i += 8)
        out[(long)(c0+i)*R + r0 + tx] = __float2bfloat16_rn(tile[tx][i]);
}

// ---------------- rmsnorm: fp32 (tf32-rounded) + bf16 outputs ----------------
__global__ __launch_bounds__(256) void rmsnorm_kernel(const float* __restrict__ in,
        const float* __restrict__ w, float* __restrict__ outf,
        __nv_bfloat16* __restrict__ outb) {
    long row = blockIdx.x;
    int t = threadIdx.x;
    float4 v = reinterpret_cast<const float4*>(in + row*DM)[t];
    float ss = v.x*v.x + v.y*v.y + v.z*v.z + v.w*v.w;
    __shared__ float red[8];
    for (int o = 16; o; o >>= 1) ss += __shfl_xor_sync(0xffffffffu, ss, o);
    if ((t & 31) == 0) red[t >> 5] = ss;
    __syncthreads();
    if (t < 32) {
        float s = (t < 8) ? red[t] : 0.f;
        for (int o = 4; o; o >>= 1) s += __shfl_xor_sync(0xffffffffu, s, o);
        if (t == 0) red[0] = s;
    }
    __syncthreads();
    float rs = rsqrtf(red[0] * (1.f/DM) + 1e-6f);
    float4 wv = reinterpret_cast<const float4*>(w)[t];
    float p0 = v.x*rs*wv.x, p1 = v.y*rs*wv.y, p2 = v.z*rs*wv.z, p3 = v.w*rs*wv.w;
    reinterpret_cast<float4*>(outf + row*DM)[t] =
        make_float4(rtf32(p0), rtf32(p1), rtf32(p2), rtf32(p3));
    __nv_bfloat162 b01, b23;
    b01.x = __float2bfloat16_rn(p0); b01.y = __float2bfloat16_rn(p1);
    b23.x = __float2bfloat16_rn(p2); b23.y = __float2bfloat16_rn(p3);
    reinterpret_cast<__nv_bfloat162*>(outb + row*DM)[t*2]   = b01;
    reinterpret_cast<__nv_bfloat162*>(outb + row*DM)[t*2+1] = b23;
}

// ---------------- h1 = x + attn ; hn (fp32 + bf16) ----------------
__global__ __launch_bounds__(256) void add_rmsnorm_kernel(const float* __restrict__ x,
        const float* __restrict__ w) {
    int row = blockIdx.x;
    int b = row / QLEN, r = row - b*QLEN;
    int t = threadIdx.x;
    float4 xv = reinterpret_cast<const float4*>(x + ((long)b*TOTAL + (TOTAL-QLEN) + r)*DM)[t];
    float4 av = reinterpret_cast<const float4*>(g_attn + (long)row*DM)[t];
    float4 hv = make_float4(xv.x+av.x, xv.y+av.y, xv.z+av.z, xv.w+av.w);
    reinterpret_cast<float4*>(g_h1 + (long)row*DM)[t] = hv;
    float ss = hv.x*hv.x + hv.y*hv.y + hv.z*hv.z + hv.w*hv.w;
    __shared__ float red[8];
    for (int o = 16; o; o >>= 1) ss += __shfl_xor_sync(0xffffffffu, ss, o);
    if ((t & 31) == 0) red[t >> 5] = ss;
    __syncthreads();
    if (t < 32) {
        float s = (t < 8) ? red[t] : 0.f;
        for (int o = 4; o; o >>= 1) s += __shfl_xor_sync(0xffffffffu, s, o);
        if (t == 0) red[0] = s;
    }
    __syncthreads();
    float rs = rsqrtf(red[0] * (1.f/DM) + 1e-6f);
    float4 wv = reinterpret_cast<const float4*>(w)[t];
    float p0 = hv.x*rs*wv.x, p1 = hv.y*rs*wv.y, p2 = hv.z*rs*wv.z, p3 = hv.w*rs*wv.w;
    reinterpret_cast<float4*>(g_hn + (long)row*DM)[t] =
        make_float4(rtf32(p0), rtf32(p1), rtf32(p2), rtf32(p3));
    __nv_bfloat162 b01, b23;
    b01.x = __float2bfloat16_rn(p0); b01.y = __float2bfloat16_rn(p1);
    b23.x = __float2bfloat16_rn(p2); b23.y = __float2bfloat16_rn(p3);
    reinterpret_cast<__nv_bfloat162*>(g_hnb + (long)row*DM)[t*2]   = b01;
    reinterpret_cast<__nv_bfloat162*>(g_hnb + (long)row*DM)[t*2+1] = b23;
}

// ---------------- BF16 tensor-core GEMM, MTILEx128x64 tiles, 3-stage cp.async ----------
template<int MTILE>
__global__ __launch_bounds__(256, 2) void mma_gemmB_kernel(
    const __nv_bfloat16* __restrict__ A, int lda, long aBatch, int rpb,
    const __nv_bfloat16* __restrict__ Bt, int ldbt,
    const float* __restrict__ bias,
    void* __restrict__ Cv, int ldc, long cBatch,
    int K, int relu, int roundOut, int outBf16,
    const int* __restrict__ seqlen, int kvSkip,
    const float* __restrict__ res)
{
    constexpr int S    = 3;
    constexpr int PAD  = 72;                 // bf16; 144B row = 9 x 16B units (odd)
    constexpr int ASTG = MTILE*PAD;
    constexpr int BSTG = 128*PAD;
    constexpr int MT   = MTILE/32;
    extern __shared__ __nv_bfloat16 smb[];
    __nv_bfloat16* AsBase = smb;
    __nv_bfloat16* BsBase = smb + S*ASTG;

    int t = threadIdx.x;
    int w = t >> 5, lane = t & 31;
    int g = lane >> 2, tig = lane & 3;
    int wm = w >> 2, wn = w & 3;

    int row0 = blockIdx.y * MTILE;
    int bn0  = blockIdx.x * 128;
    int batch = row0 / rpb;
    int rin   = row0 % rpb;
    if (kvSkip) {
        int kmin = MAXS - seqlen[batch];
        if (rin + MTILE - 1 < kmin) return;
    }
    const __nv_bfloat16* Ab = A + (long)batch*aBatch + (long)rin*lda;
    const __nv_bfloat16* Bb = Bt + (long)bn0*ldbt;

    uint32_t aSm0 = (uint32_t)__cvta_generic_to_shared(AsBase);
    uint32_t bSm0 = (uint32_t)__cvta_generic_to_shared(BsBase);

    float acc[MT][4][4];
    #pragma unroll
    for (int i = 0; i < MT; i++)
        #pragma unroll
        for (int j = 0; j < 4; j++)
            #pragma unroll
            for (int r = 0; r < 4; r++) acc[i][j][r] = 0.f;

    const int KT = K >> 6;
    auto issue = [&](int kt) {
        int s = kt % S;
        const __nv_bfloat16* ga = Ab + kt*64;
        const __nv_bfloat16* gb = Bb + kt*64;
        uint32_t aS = aSm0 + s*ASTG*2;
        uint32_t bS = bSm0 + s*BSTG*2;
        #pragma unroll
        for (int it = 0; it < MTILE/32; it++) {
            int i = t + it*256;
            int row = i >> 3, seg = i & 7;              // 8 chunks of 8 bf16 per row
            cpa16(aS + (row*PAD + seg*8)*2, ga + (long)row*lda + seg*8);
        }
        #pragma unroll
        for (int it = 0; it < 4; it++) {
            int i = t + it*256;
            int row = i >> 3, seg = i & 7;
            cpa16(bS + (row*PAD + seg*8)*2, gb + (long)row*ldbt + seg*8);
        }
        asm volatile("cp.async.commit_group;");
    };
    issue(0);
    issue(1);

    int aRow  = lane & 15;
    int aColH = (lane >> 4) * 8;
    int bRowO = ((lane >> 4) & 1)*8 + (lane & 7);
    int bColH = ((lane >> 3) & 1)*8;

    for (int kt = 0; kt < KT; kt++) {
        if (kt == KT - 1) asm volatile("cp.async.wait_group 0;");
        else              asm volatile("cp.async.wait_group 1;");
        __syncthreads();
        if (kt + 2 < KT) issue(kt + 2);

        int s = kt % S;
        uint32_t As = aSm0 + s*ASTG*2;
        uint32_t Bs = bSm0 + s*BSTG*2;
        #pragma unroll
        for (int ks = 0; ks < 4; ks++) {
            uint32_t afr[MT][4];
            #pragma unroll
            for (int mt = 0; mt < MT; mt++)
                ldsm4(afr[mt], As + ((wm*(MTILE/2) + mt*16 + aRow)*PAD + ks*16 + aColH)*2);
            uint32_t bfr[4][2];
            #pragma unroll
            for (int p = 0; p < 2; p++) {
                uint32_t r4[4];
                ldsm4(r4, Bs + ((wn*32 + p*16 + bRowO)*PAD + ks*16 + bColH)*2);
                bfr[2*p][0]   = r4[0]; bfr[2*p][1]   = r4[1];
                bfr[2*p+1][0] = r4[2]; bfr[2*p+1][1] = r4[3];
            }
            #pragma unroll
            for (int mt = 0; mt < MT; mt++)
                #pragma unroll
                for (int nt = 0; nt < 4; nt++)
                    mma_bf16(acc[mt][nt], afr[mt][0], afr[mt][1], afr[mt][2], afr[mt][3],
                             bfr[nt][0], bfr[nt][1]);
        }
    }

    float* Cf = (float*)Cv;
    __nv_bfloat16* Cb = (__nv_bfloat16*)Cv;
    #pragma unroll
    for (int nt = 0; nt < 4; nt++) {
        int col = wn*32 + nt*8 + 2*tig;
        float bx = bias[bn0 + col], by = bias[bn0 + col + 1];
        #pragma unroll
        for (int mt = 0; mt < MT; mt++) {
            int r0 = wm*(MTILE/2) + mt*16 + g;
            long base0 = (long)batch*cBatch + (long)(rin + r0)*ldc + bn0 + col;
            long base1 = base0 + (long)8*ldc;
            float c0 = acc[mt][nt][0] + bx, c1 = acc[mt][nt][1] + by;
            float c2 = acc[mt][nt][2] + bx, c3 = acc[mt][nt][3] + by;
            if (relu) { c0=fmaxf(c0,0.f); c1=fmaxf(c1,0.f); c2=fmaxf(c2,0.f); c3=fmaxf(c3,0.f); }
            if (res) {
                float2 r0v = *reinterpret_cast<const float2*>(res + base0);
                float2 r1v = *reinterpret_cast<const float2*>(res + base1);
                c0 += r0v.x; c1 += r0v.y; c2 += r1v.x; c3 += r1v.y;
            }
            if (outBf16) {
                __nv_bfloat162 v0, v1;
                v0.x = __float2bfloat16_rn(c0); v0.y = __float2bfloat16_rn(c1);
                v1.x = __float2bfloat16_rn(c2); v1.y = __float2bfloat16_rn(c3);
                *reinterpret_cast<__nv_bfloat162*>(Cb + base0) = v0;
                *reinterpret_cast<__nv_bfloat162*>(Cb + base1) = v1;
            } else {
                if (roundOut) { c0=rtf32(c0); c1=rtf32(c1); c2=rtf32(c2); c3=rtf32(c3); }
                *reinterpret_cast<float2*>(Cf + base0) = make_float2(c0, c1);
                *reinterpret_cast<float2*>(Cf + base1) = make_float2(c2, c3);
            }
        }
    }
}

// ---------------- per-NS-position linear: vectorized K-split partials ----------------
__global__ __launch_bounds__(128) void ns_split4_kernel(
    const float* __restrict__ X, long xBatch, int xRow,
    const float* __restrict__ W, float* __restrict__ part,
    int K, int N, int kchunk)
{
    __shared__ float Xs[4][512];
    int n = blockIdx.y, z = blockIdx.z;
    int t = threadIdx.x;
    int o4 = (blockIdx.x*128 + t)*4;
    int k0 = z*kchunk;
    for (int i = t; i < kchunk; i += 128) {
        long xo = (long)n*xRow + k0 + i;
        Xs[0][i] = X[0*xBatch + xo];
        Xs[1][i] = X[1*xBatch + xo];
        Xs[2][i] = X[2*xBatch + xo];
        Xs[3][i] = X[3*xBatch + xo];
    }
    __syncthreads();
    const float* Wp = W + (long)n*K*N + (long)k0*N + o4;
    float acc[4][4];
    #pragma unroll
    for (int b = 0; b < 4; b++)
        #pragma unroll
        for (int j = 0; j < 4; j++) acc[b][j] = 0.f;
    #pragma unroll 8
    for (int k = 0; k < kchunk; k++) {
        float4 wv = *reinterpret_cast<const float4*>(Wp + (long)k*N);
        #pragma unroll
        for (int b = 0; b < 4; b++) {
            float xv = Xs[b][k];
            acc[b][0] += xv*wv.x; acc[b][1] += xv*wv.y;
            acc[b][2] += xv*wv.z; acc[b][3] += xv*wv.w;
        }
    }
    #pragma unroll
    for (int b = 0; b < 4; b++)
        *reinterpret_cast<float4*>(&part[((long)(z*BSZ+b)*NSN + n)*N + o4]) =
            make_float4(acc[b][0], acc[b][1], acc[b][2], acc[b][3]);
}

__global__ __launch_bounds__(256) void ns_reduce_kernel(
    const float* __restrict__ part, const float* __restrict__ bias,
    float* __restrict__ Y, long yBatch, int yRow, int N, int KS, int relu, int roundOut,
    const float* __restrict__ res)
{
    int o = blockIdx.x*256 + threadIdx.x;
    int n = blockIdx.y, b = blockIdx.z;
    float s = bias[(long)n*N + o];
    for (int z = 0; z < KS; z++)
        s += part[((long)(z*BSZ+b)*NSN + n)*N + o];
    if (relu) s = fmaxf(s, 0.f);
    if (roundOut) s = rtf32(s);
    long idx = (long)b*yBatch + (long)n*yRow + o;
    if (res) s += res[idx];
    Y[idx] = s;
}

// ---------------- RoPE in-place (fp32 path, rounded output) ----------------
__global__ void rope_kernel(float* __restrict__ buf, int rowsPerB, int pos0, int rstride, int total) {
    int idx = blockIdx.x*blockDim.x + threadIdx.x;
    if (idx >= total) return;
    int j  = idx & 31;
    int h  = (idx >> 5) & (NH-1);
    int rr = idx >> 9;
    int b  = rr / rowsPerB;
    int r  = rr - b*rowsPerB;
    float inv = exp2f(-(float)j * 0.41524101186092029f);
    double ang = (double)(pos0 + r) * (double)inv;
    const double TWO_PI = 6.2831853071795864769;
    double red = ang - TWO_PI * rint(ang * (1.0/6.2831853071795864769));
    float rf = (float)red;
    float s, c;
    sincosf(rf, &s, &c);
    float* base = buf + ((long)b*rowsPerB + r)*(long)rstride + h*HD;
    float x1 = base[j], x2 = base[j+32];
    base[j]    = rtf32(x1*c - x2*s);
    base[j+32] = rtf32(x2*c + x1*s);
}

// ---------------- tf32 flash attention, 64-key tiles, Q frags hoisted ----------
#define ATT_QS(r,c)      dsm[(r)*68 + (c)]
#define ATT_KS(bf,r,c)   dsm[4352 + (bf)*4352 + (r)*68 + (c)]
#define ATT_VS(bf,r,c)   dsm[13056 + (bf)*4608 + (r)*72 + (c)]
#define ATT_SS(r,c)      dsm[22272 + (r)*68 + (c)]
#define ATT_SMEM_FLOATS  (26752 + 128)

__global__ __launch_bounds__(256, 2) void attn_mma_kernel(
    const float* __restrict__ q, const float* __restrict__ kv,
    float* __restrict__ attn, const int* __restrict__ seqlen)
{
    extern __shared__ float dsm[];
    float* corrs = dsm + 26752;
    float* lrow  = corrs + 64;

    int qt = blockIdx.x, h = blockIdx.y, b = blockIdx.z;
    int tid = threadIdx.x;
    int w = tid >> 5, lane = tid & 31;
    int g = lane >> 2, tig = lane & 3;
    int wm = w >> 2, wn = w & 3;
    int L = seqlen[b];
    int kmin = MAXS - L;

    for (int i = tid; i < 64*16; i += 256) {
        int r = i >> 4, c4 = (i & 15) * 4;
        int qg = qt*64 + r;
        float4 val = make_float4(0.f,0.f,0.f,0.f);
        if (qg < QLEN)
            val = *reinterpret_cast<const float4*>(q + ((long)b*QLEN + qg)*DM + h*HD + c4);
        *reinterpret_cast<float4*>(&ATT_QS(r, c4)) = val;
    }

    int srow = tid >> 2, ssub = tid & 3;
    float m = -1e30f, l = 0.f;

    float oacc[2][2][4];
    #pragma unroll
    for (int i = 0; i < 2; i++)
        #pragma unroll
        for (int j = 0; j < 2; j++)
            #pragma unroll
            for (int r = 0; r < 4; r++) oacc[i][j][r] = 0.f;

    int qgmax = min(QLEN-1, qt*64 + 63);
    int t0 = kmin >> 6;
    int t1 = (MAXS - OUTN + qgmax) >> 6;

    uint32_t smBase = (uint32_t)__cvta_generic_to_shared(dsm);

    auto loadTile = [&](int kt) {
        int buf = kt & 1;
        int key0 = kt * 64;
        #pragma unroll
        for (int it = 0; it < 4; it++) {
            int i = tid + it*256;
            int r = i >> 4;
            int c4 = (i & 15) * 4;
            int key = key0 + r;
            long off = ((long)b*TOTAL + min(key, TOTAL-1))*(2*DM) + h*HD + c4;
            cpa16(smBase + (4352 + buf*4352 + r*68 + c4)*4, kv + off);
            cpa16(smBase + (13056 + buf*4608 + r*72 + c4)*4, kv + off + DM);
        }
        asm volatile("cp.async.commit_group;");
    };
    loadTile(t0);
    asm volatile("cp.async.commit_group;");

    // hoist Q fragments (constant over key tiles)
    __syncthreads();
    uint32_t qfr[8][2][4];
    #pragma unroll
    for (int dk = 0; dk < 8; dk++)
        #pragma unroll
        for (int mt = 0; mt < 2; mt++) {
            int m0 = wm*32 + mt*16;
            qfr[dk][mt][0] = f2u(ATT_QS(m0+g,   dk*8+tig));
            qfr[dk][mt][1] = f2u(ATT_QS(m0+g+8, dk*8+tig));
            qfr[dk][mt][2] = f2u(ATT_QS(m0+g,   dk*8+tig+4));
            qfr[dk][mt][3] = f2u(ATT_QS(m0+g+8, dk*8+tig+4));
        }

    for (int kt = t0; kt <= t1; kt++) {
        int key0 = kt * 64;
        int buf = kt & 1;
        asm volatile("cp.async.wait_group 1;");
        __syncthreads();
        if (kt + 1 <= t1) loadTile(kt + 1);
        else              asm volatile("cp.async.commit_group;");

        float sa[2][2][4];
        #pragma unroll
        for (int mt = 0; mt < 2; mt++)
            #pragma unroll
            for (int kn = 0; kn < 2; kn++)
                #pragma unroll
                for (int r = 0; r < 4; r++) sa[mt][kn][r] = 0.f;
        #pragma unroll
        for (int dk = 0; dk < 8; dk++) {
            #pragma unroll
            for (int kn = 0; kn < 2; kn++) {
                uint32_t bf0 = f2u(ATT_KS(buf, wn*16 + kn*8 + g, dk*8 + tig));
                uint32_t bf1 = f2u(ATT_KS(buf, wn*16 + kn*8 + g, dk*8 + tig + 4));
                #pragma unroll
                for (int mt = 0; mt < 2; mt++)
                    mma_tf32(sa[mt][kn], qfr[dk][mt][0], qfr[dk][mt][1],
                             qfr[dk][mt][2], qfr[dk][mt][3], bf0, bf1);
            }
        }
        #pragma unroll
        for (int mt = 0; mt < 2; mt++) {
            #pragma unroll
            for (int kn = 0; kn < 2; kn++) {
                #pragma unroll
                for (int hh = 0; hh < 2; hh++) {
                    int r = wm*32 + mt*16 + g + hh*8;
                    int qg = qt*64 + r;
                    int col = wn*16 + kn*8 + 2*tig;
                    int key = key0 + col;
                    int kcap = MAXS - OUTN + qg;
                    bool rowok = (qg < QLEN);
                    float sA = sa[mt][kn][hh*2+0], sB = sa[mt][kn][hh*2+1];
                    bool v0 = rowok && (key   < TOTAL) && (key   >= kmin) && (key   <= kcap);
                    bool v1 = rowok && (key+1 < TOTAL) && (key+1 >= kmin) && (key+1 <= kcap);
                    ATT_SS(r, col)     = v0 ? sA*0.125f : -1e9f;
                    ATT_SS(r, col + 1) = v1 ? sB*0.125f : -1e9f;
                }
            }
        }
        __syncthreads();

        float sv[16];
        #pragma unroll
        for (int j = 0; j < 16; j++) sv[j] = ATT_SS(srow, ssub*16 + j);
        float tmax = sv[0];
        #pragma unroll
        for (int j = 1; j < 16; j++) tmax = fmaxf(tmax, sv[j]);
        tmax = fmaxf(tmax, __shfl_xor_sync(0xffffffffu, tmax, 1));
        tmax = fmaxf(tmax, __shfl_xor_sync(0xffffffffu, tmax, 2));
        float corr = 1.f;
        if (tmax > -1e8f) {
            float m_new = fmaxf(m, tmax);
            corr = __expf(m - m_new);
            float ps = 0.f;
            #pragma unroll
            for (int j = 0; j < 16; j++) {
                float p = __expf(sv[j] - m_new);
                ps += p;
                ATT_SS(srow, ssub*16 + j) = rtf32(p);
            }
            ps += __shfl_xor_sync(0xffffffffu, ps, 1);
            ps += __shfl_xor_sync(0xffffffffu, ps, 2);
            l = l*corr + ps;
            m = m_new;
        } else {
            #pragma unroll
            for (int j = 0; j < 16; j++) ATT_SS(srow, ssub*16 + j) = 0.f;
        }
        if (ssub == 0) corrs[srow] = corr;
        __syncthreads();

        #pragma unroll
        for (int mt = 0; mt < 2; mt++) {
            float c0 = corrs[wm*32 + mt*16 + g];
            float c1 = corrs[wm*32 + mt*16 + g + 8];
            #pragma unroll
            for (int nt = 0; nt < 2; nt++) {
                oacc[mt][nt][0] *= c0; oacc[mt][nt][1] *= c0;
                oacc[mt][nt][2] *= c1; oacc[mt][nt][3] *= c1;
            }
        }
        #pragma unroll
        for (int kd = 0; kd < 8; kd++) {
            uint32_t bf[2][2];
            #pragma unroll
            for (int nt = 0; nt < 2; nt++) {
                int n = wn*16 + nt*8 + g;
                bf[nt][0] = f2u(ATT_VS(buf, kd*8 + tig,     n));
                bf[nt][1] = f2u(ATT_VS(buf, kd*8 + tig + 4, n));
            }
            #pragma unroll
            for (int mt = 0; mt < 2; mt++) {
                int m0 = wm*32 + mt*16;
                uint32_t a0 = f2u(ATT_SS(m0+g,   kd*8+tig));
                uint32_t a1 = f2u(ATT_SS(m0+g+8, kd*8+tig));
                uint32_t a2 = f2u(ATT_SS(m0+g,   kd*8+tig+4));
                uint32_t a3 = f2u(ATT_SS(m0+g+8, kd*8+tig+4));
                #pragma unroll
                for (int nt = 0; nt < 2; nt++)
                    mma_tf32(oacc[mt][nt], a0, a1, a2, a3, bf[nt][0], bf[nt][1]);
            }
        }
        // NOTE: no end-of-loop barrier needed — next iteration's top __syncthreads
        // orders this iteration's ssm/vsm reads before any subsequent overwrite.
    }

    if (ssub == 0) lrow[srow] = l;
    __syncthreads();
    #pragma unroll
    for (int mt = 0; mt < 2; mt++) {
        #pragma unroll
        for (int hh = 0; hh < 2; hh++) {
            int r = wm*32 + mt*16 + g + hh*8;
            int qg = qt*64 + r;
            if (qg < QLEN) {
                float invl = 1.f / lrow[r];
                #pragma unroll
                for (int nt = 0; nt < 2; nt++) {
                    int col = wn*16 + nt*8 + 2*tig;
                    *reinterpret_cast<float2*>(attn + ((long)b*QLEN + qg)*DM + h*HD + col)
                        = make_float2(oacc[mt][nt][hh*2]*invl, oacc[mt][nt][hh*2+1]*invl);
                }
            }
        }
    }
}

// ---------------- tail: optional seqlen extras ----------------
__global__ void tail_kernel(float* __restrict__ out, const int* __restrict__ seqlen, int out_size) {
    int b = threadIdx.x;
    const int main_n = BSZ*QLEN*DM;
    if (b < BSZ && out_size >= main_n + BSZ) {
        int L = seqlen[b];
        out[main_n + b] = (float)(L < OUTN ? L : OUTN);
    }
}

extern "C" void kernel_launch(void* const* d_in, const int* in_sizes, int n_in,
                              void* d_out, int out_size) {
    (void)in_sizes; (void)n_in;
    const float* x    = (const float*)d_in[0];
    const int*   seq  = (const int*)  d_in[1];
    const float* wqkv = (const float*)d_in[2];
    const float* bqkv = (const float*)d_in[3];
    const float* wnsq = (const float*)d_in[4];
    const float* bnsq = (const float*)d_in[5];
    const float* wnsk = (const float*)d_in[6];
    const float* bnsk = (const float*)d_in[7];
    const float* wnsv = (const float*)d_in[8];
    const float* bnsv = (const float*)d_in[9];
    const float* n1w  = (const float*)d_in[10];
    const float* n2w  = (const float*)d_in[11];
    const float* fw1  = (const float*)d_in[12];
    const float* fb1  = (const float*)d_in[13];
    const float* fw2  = (const float*)d_in[14];
    const float* fb2  = (const float*)d_in[15];
    const float* w1ns = (const float*)d_in[16];
    const float* b1ns = (const float*)d_in[17];
    const float* w2ns = (const float*)d_in[18];
    const float* b2ns = (const float*)d_in[19];
    float* out = (float*)d_out;

    float *xn,*q,*kv,*attn,*h1,*hn,*tns,*fns,*part;
    __nv_bfloat16 *xnb,*hnb,*tsb,*wqb,*w1b,*w2b;
    cudaGetSymbolAddress((void**)&xn,   g_xn);
    cudaGetSymbolAddress((void**)&q,    g_q);
    cudaGetSymbolAddress((void**)&kv,   g_kv);
    cudaGetSymbolAddress((void**)&attn, g_attn);
    cudaGetSymbolAddress((void**)&h1,   g_h1);
    cudaGetSymbolAddress((void**)&hn,   g_hn);
    cudaGetSymbolAddress((void**)&tns,  g_tns);
    cudaGetSymbolAddress((void**)&fns,  g_fns);
    cudaGetSymbolAddress((void**)&part, g_part);
    cudaGetSymbolAddress((void**)&xnb,  g_xnb);
    cudaGetSymbolAddress((void**)&hnb,  g_hnb);
    cudaGetSymbolAddress((void**)&tsb,  g_tsb);
    cudaGetSymbolAddress((void**)&wqb,  g_wqkvb);
    cudaGetSymbolAddress((void**)&w1b,  g_w1b);
    cudaGetSymbolAddress((void**)&w2b,  g_w2b);
    float* part2 = part + 2*1024*1024;

    const long aB  = (long)TOTAL*DM;
    const long qB  = (long)QLEN*DM;
    const long kvB = (long)TOTAL*2*DM;

    const int SMEMB128 = (3*128*72 + 3*128*72) * 2;   // 110592 B
    const int SMEMB64  = (3*64*72  + 3*128*72) * 2;   //  82944 B
    const int ATTSMEM  = ATT_SMEM_FLOATS * 4;
    cudaFuncSetAttribute(mma_gemmB_kernel<128>, cudaFuncAttributeMaxDynamicSharedMemorySize, SMEMB128);
    cudaFuncSetAttribute(mma_gemmB_kernel<64>,  cudaFuncAttributeMaxDynamicSharedMemorySize, SMEMB64);
    cudaFuncSetAttribute(attn_mma_kernel, cudaFuncAttributeMaxDynamicSharedMemorySize, ATTSMEM);

    static cudaStream_t s1 = nullptr, s2 = nullptr, s3 = nullptr;
    static cudaEvent_t  eB, e0, e1, e2, e2a, e3, e4, e5;
    if (s1 == nullptr) {
        cudaStreamCreateWithFlags(&s1, cudaStreamNonBlocking);
        cudaStreamCreateWithFlags(&s2, cudaStreamNonBlocking);
        cudaStreamCreateWithFlags(&s3, cudaStreamNonBlocking);
        cudaEventCreateWithFlags(&eB,  cudaEventDisableTiming);
        cudaEventCreateWithFlags(&e0,  cudaEventDisableTiming);
        cudaEventCreateWithFlags(&e1,  cudaEventDisableTiming);
        cudaEventCreateWithFlags(&e2,  cudaEventDisableTiming);
        cudaEventCreateWithFlags(&e2a, cudaEventDisableTiming);
        cudaEventCreateWithFlags(&e3,  cudaEventDisableTiming);
        cudaEventCreateWithFlags(&e4,  cudaEventDisableTiming);
        cudaEventCreateWithFlags(&e5,  cudaEventDisableTiming);
    }
    cudaStream_t s0 = 0;

    // ---- Phase 1 : rmsnorm (s0) || weight transposes (s2) ----
    cudaEventRecord(eB, s0);
    cudaStreamWaitEvent(s2, eB, 0);
    transpose_bf16_kernel<<<dim3(3*DM/32, DM/32), dim3(32,8), 0, s2>>>(wqkv, wqb, DM, 3*DM);
    cudaEventRecord(e2a, s2);
    transpose_bf16_kernel<<<dim3(FFND/32, DM/32), dim3(32,8), 0, s2>>>(fw1, w1b, DM, FFND);
    transpose_bf16_kernel<<<dim3(DM/32, FFND/32), dim3(32,8), 0, s2>>>(fw2, w2b, FFND, DM);
    cudaEventRecord(e2, s2);

    rmsnorm_kernel<<<BSZ*TOTAL, 256, 0, s0>>>(x, n1w, xn, xnb);
    cudaEventRecord(e0, s0);

    // s1: Q projection -> ns_q -> rope_q
    cudaStreamWaitEvent(s1, e0, 0);
    cudaStreamWaitEvent(s1, e2a, 0);
    mma_gemmB_kernel<64><<<dim3(DM/128, (BSZ*OUTN)/64), 256, SMEMB64, s1>>>(
        xnb + (long)(MAXS-OUTN)*DM, DM, aB, OUTN, wqb, DM, bqkv, q, DM, qB, DM, 0, 1, 0, seq, 0, nullptr);
    ns_split4_kernel<<<dim3(DM/512, NSN, 32), 128, 0, s1>>>(xn + (long)MAXS*DM, aB, DM, wnsq, part2, DM, DM, DM/32);
    ns_reduce_kernel<<<dim3(DM/256, NSN, BSZ), 256, 0, s1>>>(part2, bnsq, q + (long)OUTN*DM, qB, DM, DM, 32, 0, 1, nullptr);
    {
        int totq = BSZ*QLEN*NH*32;
        rope_kernel<<<(totq+255)/256, 256, 0, s1>>>(q, QLEN, TOTAL-QLEN, DM, totq);
    }
    cudaEventRecord(e1, s1);

    // s3: ns_v then ns_k
    cudaStreamWaitEvent(s3, e0, 0);
    ns_split4_kernel<<<dim3(DM/512, NSN, 32), 128, 0, s3>>>(xn + (long)MAXS*DM, aB, DM, wnsv, part, DM, DM, DM/32);
    ns_reduce_kernel<<<dim3(DM/256, NSN, BSZ), 256, 0, s3>>>(part, bnsv, kv + (long)MAXS*2*DM + DM, kvB, 2*DM, DM, 32, 0, 1, nullptr);
    ns_split4_kernel<<<dim3(DM/512, NSN, 32), 128, 0, s3>>>(xn + (long)MAXS*DM, aB, DM, wnsk, part, DM, DM, DM/32);
    ns_reduce_kernel<<<dim3(DM/256, NSN, BSZ), 256, 0, s3>>>(part, bnsk, kv + (long)MAXS*2*DM, kvB, 2*DM, DM, 32, 0, 1, nullptr);
    cudaEventRecord(e3, s3);

    // s0: KV projection, then rope_k
    cudaStreamWaitEvent(s0, e2a, 0);
    mma_gemmB_kernel<128><<<dim3(2*DM/128, (BSZ*MAXS)/128), 256, SMEMB128, s0>>>(xnb, DM, aB, MAXS,
        wqb + (long)DM*DM, DM, bqkv + DM, kv, 2*DM, kvB, DM, 0, 1, 0, seq, 1, nullptr);
    cudaStreamWaitEvent(s0, e3, 0);
    {
        int totk = BSZ*TOTAL*NH*32;
        rope_kernel<<<(totk+255)/256, 256, 0, s0>>>(kv, TOTAL, 0, 2*DM, totk);
    }

    cudaStreamWaitEvent(s0, e1, 0);
    attn_mma_kernel<<<dim3((QLEN+63)/64, NH, BSZ), 256, ATTSMEM, s0>>>(q, kv, attn, seq);

    add_rmsnorm_kernel<<<BSZ*QLEN, 256, 0, s0>>>(x, n2w);
    cudaEventRecord(e4, s0);

    // ---- Phase 2 ----
    cudaStreamWaitEvent(s1, e4, 0);
    ns_split4_kernel<<<dim3(FFND/512, NSN, 16), 128, 0, s1>>>(hn + (long)OUTN*DM, qB, DM, w1ns, part, DM, FFND, DM/16);
    ns_reduce_kernel<<<dim3(FFND/256, NSN, BSZ), 256, 0, s1>>>(part, b1ns, tns, (long)NSN*FFND, FFND, FFND, 16, 1, 0, nullptr);
    ns_split4_kernel<<<dim3(DM/512, NSN, 32), 128, 0, s1>>>(tns, (long)NSN*FFND, FFND, w2ns, part, FFND, DM, FFND/32);
    ns_reduce_kernel<<<dim3(DM/256, NSN, BSZ), 256, 0, s1>>>(part, b2ns,
        out + (long)OUTN*DM, qB, DM, DM, 32, 0, 0, h1 + (long)OUTN*DM);
    cudaEventRecord(e5, s1);

    cudaStreamWaitEvent(s0, e2, 0);
    mma_gemmB_kernel<128><<<dim3(FFND/128, (BSZ*OUTN)/128), 256, SMEMB128, s0>>>(hnb, DM, qB, OUTN,
        w1b, DM, fb1, tsb, FFND, (long)OUTN*FFND, DM, 1, 0, 1, seq, 0, nullptr);
    mma_gemmB_kernel<64><<<dim3(DM/128, (BSZ*OUTN)/64), 256, SMEMB64, s0>>>(tsb, FFND, (long)OUTN*FFND, OUTN,
        w2b, FFND, fb2, out, DM, qB, FFND, 0, 0, 0, seq, 0, h1);

    cudaStreamWaitEvent(s0, e5, 0);
    tail_kernel<<<1, BSZ, 0, s0>>>(out, seq, out_size);
}

// round 16
// speedup vs baseline: 1.0479x; 1.0479x over previous
#include <cuda_runtime.h>
#include <cuda_bf16.h>
#include <cstdint>

#define BSZ   4
#define TOTAL 2064
#define DM    1024
#define NSN   16
#define OUTN  256
#define QLEN  272
#define NH    16
#define HD    64
#define FFND  4096
#define MAXS  2048

// Scratch (static device globals; no allocation allowed)
__device__ float g_xn  [BSZ*TOTAL*DM];
__device__ float g_q   [BSZ*QLEN*DM];
__device__ float g_kv  [BSZ*TOTAL*2*DM];
__device__ float g_attn[BSZ*QLEN*DM];
__device__ float g_h1  [BSZ*QLEN*DM];
__device__ float g_hn  [BSZ*QLEN*DM];
__device__ float g_tns [BSZ*NSN*FFND];
__device__ float g_fns [BSZ*NSN*DM];
__device__ float g_part[4*1024*1024];
// bf16 activations + transposed bf16 weights ([N,K] row-major)
__device__ __nv_bfloat16 g_xnb [BSZ*TOTAL*DM];
__device__ __nv_bfloat16 g_hnb [BSZ*QLEN*DM];
__device__ __nv_bfloat16 g_tsb [BSZ*OUTN*FFND];
__device__ __nv_bfloat16 g_wqkvb[3*DM*DM];
__device__ __nv_bfloat16 g_w1b  [FFND*DM];
__device__ __nv_bfloat16 g_w2b  [DM*FFND];

__device__ __forceinline__ float rtf32(float x) {
    uint32_t u;
    asm("cvt.rna.tf32.f32 %0, %1;" : "=r"(u) : "f"(x));
    return __uint_as_float(u);
}
__device__ __forceinline__ uint32_t f2u(float x) { return __float_as_uint(x); }

__device__ __forceinline__ void cpa16(uint32_t dst, const void* src) {
    asm volatile("cp.async.ca.shared.global [%0], [%1], 16;" :: "r"(dst), "l"(src));
}

__device__ __forceinline__ void mma_tf32(float* c,
        uint32_t a0, uint32_t a1, uint32_t a2, uint32_t a3,
        uint32_t b0, uint32_t b1) {
    asm volatile(
        "mma.sync.aligned.m16n8k8.row.col.f32.tf32.tf32.f32 "
        "{%0,%1,%2,%3}, {%4,%5,%6,%7}, {%8,%9}, {%0,%1,%2,%3};\n"
        : "+f"(c[0]), "+f"(c[1]), "+f"(c[2]), "+f"(c[3])
        : "r"(a0), "r"(a1), "r"(a2), "r"(a3), "r"(b0), "r"(b1));
}
__device__ __forceinline__ void mma_bf16(float* c,
        uint32_t a0, uint32_t a1, uint32_t a2, uint32_t a3,
        uint32_t b0, uint32_t b1) {
    asm volatile(
        "mma.sync.aligned.m16n8k16.row.col.f32.bf16.bf16.f32 "
        "{%0,%1,%2,%3}, {%4,%5,%6,%7}, {%8,%9}, {%0,%1,%2,%3};\n"
        : "+f"(c[0]), "+f"(c[1]), "+f"(c[2]), "+f"(c[3])
        : "r"(a0), "r"(a1), "r"(a2), "r"(a3), "r"(b0), "r"(b1));
}

__device__ __forceinline__ void ldsm4(uint32_t* r, uint32_t addr) {
    asm volatile("ldmatrix.sync.aligned.m8n8.x4.shared.b16 {%0,%1,%2,%3}, [%4];"
        : "=r"(r[0]), "=r"(r[1]), "=r"(r[2]), "=r"(r[3]) : "r"(addr));
}

// ---------------- transpose + bf16 convert ----------------
__global__ __launch_bounds__(256) void transpose_bf16_kernel(const float* __restrict__ in,
        __nv_bfloat16* __restrict__ out, int R, int C) {
    __shared__ float tile[32][33];
    int c0 = blockIdx.x*32, r0 = blockIdx.y*32;
    int tx = threadIdx.x, ty = threadIdx.y;
    for (int i = ty; i < 32; i += 8)
        tile[i][tx] = in[(long)(r0+i)*C + c0 + tx];
    __syncthreads();
    for (int i = ty; i < 32; i += 8)
        out[(long)(c0+i)*R + r0 + tx] = __float2bfloat16_rn(tile[tx][i]);
}

// ---------------- rmsnorm: fp32 (tf32-rounded) + bf16 outputs ----------------
__global__ __launch_bounds__(256) void rmsnorm_kernel(const float* __restrict__ in,
        const float* __restrict__ w, float* __restrict__ outf,
        __nv_bfloat16* __restrict__ outb) {
    long row = blockIdx.x;
    int t = threadIdx.x;
    float4 v = reinterpret_cast<const float4*>(in + row*DM)[t];
    float ss = v.x*v.x + v.y*v.y + v.z*v.z + v.w*v.w;
    __shared__ float red[8];
    for (int o = 16; o; o >>= 1) ss += __shfl_xor_sync(0xffffffffu, ss, o);
    if ((t & 31) == 0) red[t >> 5] = ss;
    __syncthreads();
    if (t < 32) {
        float s = (t < 8) ? red[t] : 0.f;
        for (int o = 4; o; o >>= 1) s += __shfl_xor_sync(0xffffffffu, s, o);
        if (t == 0) red[0] = s;
    }
    __syncthreads();
    float rs = rsqrtf(red[0] * (1.f/DM) + 1e-6f);
    float4 wv = reinterpret_cast<const float4*>(w)[t];
    float p0 = v.x*rs*wv.x, p1 = v.y*rs*wv.y, p2 = v.z*rs*wv.z, p3 = v.w*rs*wv.w;
    reinterpret_cast<float4*>(outf + row*DM)[t] =
        make_float4(rtf32(p0), rtf32(p1), rtf32(p2), rtf32(p3));
    __nv_bfloat162 b01, b23;
    b01.x = __float2bfloat16_rn(p0); b01.y = __float2bfloat16_rn(p1);
    b23.x = __float2bfloat16_rn(p2); b23.y = __float2bfloat16_rn(p3);
    reinterpret_cast<__nv_bfloat162*>(outb + row*DM)[t*2]   = b01;
    reinterpret_cast<__nv_bfloat162*>(outb + row*DM)[t*2+1] = b23;
}

// ---------------- h1 = x + attn ; hn (fp32 + bf16) ----------------
__global__ __launch_bounds__(256) void add_rmsnorm_kernel(const float* __restrict__ x,
        const float* __restrict__ w) {
    int row = blockIdx.x;
    int b = row / QLEN, r = row - b*QLEN;
    int t = threadIdx.x;
    float4 xv = reinterpret_cast<const float4*>(x + ((long)b*TOTAL + (TOTAL-QLEN) + r)*DM)[t];
    float4 av = reinterpret_cast<const float4*>(g_attn + (long)row*DM)[t];
    float4 hv = make_float4(xv.x+av.x, xv.y+av.y, xv.z+av.z, xv.w+av.w);
    reinterpret_cast<float4*>(g_h1 + (long)row*DM)[t] = hv;
    float ss = hv.x*hv.x + hv.y*hv.y + hv.z*hv.z + hv.w*hv.w;
    __shared__ float red[8];
    for (int o = 16; o; o >>= 1) ss += __shfl_xor_sync(0xffffffffu, ss, o);
    if ((t & 31) == 0) red[t >> 5] = ss;
    __syncthreads();
    if (t < 32) {
        float s = (t < 8) ? red[t] : 0.f;
        for (int o = 4; o; o >>= 1) s += __shfl_xor_sync(0xffffffffu, s, o);
        if (t == 0) red[0] = s;
    }
    __syncthreads();
    float rs = rsqrtf(red[0] * (1.f/DM) + 1e-6f);
    float4 wv = reinterpret_cast<const float4*>(w)[t];
    float p0 = hv.x*rs*wv.x, p1 = hv.y*rs*wv.y, p2 = hv.z*rs*wv.z, p3 = hv.w*rs*wv.w;
    reinterpret_cast<float4*>(g_hn + (long)row*DM)[t] =
        make_float4(rtf32(p0), rtf32(p1), rtf32(p2), rtf32(p3));
    __nv_bfloat162 b01, b23;
    b01.x = __float2bfloat16_rn(p0); b01.y = __float2bfloat16_rn(p1);
    b23.x = __float2bfloat16_rn(p2); b23.y = __float2bfloat16_rn(p3);
    reinterpret_cast<__nv_bfloat162*>(g_hnb + (long)row*DM)[t*2]   = b01;
    reinterpret_cast<__nv_bfloat162*>(g_hnb + (long)row*DM)[t*2+1] = b23;
}

// ---------------- BF16 tensor-core GEMM, MTILEx128x32, 3-stage cp.async (round-14 proven) --
template<int MTILE>
__global__ __launch_bounds__(256, 2) void mma_gemmB_kernel(
    const __nv_bfloat16* __restrict__ A, int lda, long aBatch, int rpb,
    const __nv_bfloat16* __restrict__ Bt, int ldbt,
    const float* __restrict__ bias,
    void* __restrict__ Cv, int ldc, long cBatch,
    int K, int relu, int roundOut, int outBf16,
    const int* __restrict__ seqlen, int kvSkip,
    const float* __restrict__ res)
{
    constexpr int S    = 3;
    constexpr int PAD  = 40;
    constexpr int ASTG = MTILE*PAD;
    constexpr int BSTG = 128*PAD;
    constexpr int MT   = MTILE/32;
    extern __shared__ __nv_bfloat16 smb[];
    __nv_bfloat16* AsBase = smb;
    __nv_bfloat16* BsBase = smb + S*ASTG;

    int t = threadIdx.x;
    int w = t >> 5, lane = t & 31;
    int g = lane >> 2, tig = lane & 3;
    int wm = w >> 2, wn = w & 3;

    int row0 = blockIdx.y * MTILE;
    int bn0  = blockIdx.x * 128;
    int batch = row0 / rpb;
    int rin   = row0 % rpb;
    if (kvSkip) {
        int kmin = MAXS - seqlen[batch];
        if (rin + MTILE - 1 < kmin) return;
    }
    const __nv_bfloat16* Ab = A + (long)batch*aBatch + (long)rin*lda;
    const __nv_bfloat16* Bb = Bt + (long)bn0*ldbt;

    uint32_t aSm0 = (uint32_t)__cvta_generic_to_shared(AsBase);
    uint32_t bSm0 = (uint32_t)__cvta_generic_to_shared(BsBase);

    float acc[MT][4][4];
    #pragma unroll
    for (int i = 0; i < MT; i++)
        #pragma unroll
        for (int j = 0; j < 4; j++)
            #pragma unroll
            for (int r = 0; r < 4; r++) acc[i][j][r] = 0.f;

    const int KT = K >> 5;
    auto issue = [&](int kt) {
        int s = kt % S;
        const __nv_bfloat16* ga = Ab + kt*32;
        const __nv_bfloat16* gb = Bb + kt*32;
        uint32_t aS = aSm0 + s*ASTG*2;
        uint32_t bS = bSm0 + s*BSTG*2;
        #pragma unroll
        for (int it = 0; it < MTILE/64; it++) {
            int i = t + it*256;
            int row = i >> 2, seg = i & 3;
            cpa16(aS + (row*PAD + seg*8)*2, ga + (long)row*lda + seg*8);
        }
        #pragma unroll
        for (int it = 0; it < 2; it++) {
            int i = t + it*256;
            int row = i >> 2, seg = i & 3;
            cpa16(bS + (row*PAD + seg*8)*2, gb + (long)row*ldbt + seg*8);
        }
        asm volatile("cp.async.commit_group;");
    };
    issue(0);
    issue(1);

    int aRow  = lane & 15;
    int aColH = (lane >> 4) * 8;
    int bRowO = ((lane >> 4) & 1)*8 + (lane & 7);
    int bColH = ((lane >> 3) & 1)*8;

    for (int kt = 0; kt < KT; kt++) {
        if (kt == KT - 1) asm volatile("cp.async.wait_group 0;");
        else              asm volatile("cp.async.wait_group 1;");
        __syncthreads();
        if (kt + 2 < KT) issue(kt + 2);

        int s = kt % S;
        uint32_t As = aSm0 + s*ASTG*2;
        uint32_t Bs = bSm0 + s*BSTG*2;
        #pragma unroll
        for (int ks = 0; ks < 2; ks++) {
            uint32_t afr[MT][4];
            #pragma unroll
            for (int mt = 0; mt < MT; mt++)
                ldsm4(afr[mt], As + ((wm*(MTILE/2) + mt*16 + aRow)*PAD + ks*16 + aColH)*2);
            uint32_t bfr[4][2];
            #pragma unroll
            for (int p = 0; p < 2; p++) {
                uint32_t r4[4];
                ldsm4(r4, Bs + ((wn*32 + p*16 + bRowO)*PAD + ks*16 + bColH)*2);
                bfr[2*p][0]   = r4[0]; bfr[2*p][1]   = r4[1];
                bfr[2*p+1][0] = r4[2]; bfr[2*p+1][1] = r4[3];
            }
            #pragma unroll
            for (int mt = 0; mt < MT; mt++)
                #pragma unroll
                for (int nt = 0; nt < 4; nt++)
                    mma_bf16(acc[mt][nt], afr[mt][0], afr[mt][1], afr[mt][2], afr[mt][3],
                             bfr[nt][0], bfr[nt][1]);
        }
    }

    float* Cf = (float*)Cv;
    __nv_bfloat16* Cb = (__nv_bfloat16*)Cv;
    #pragma unroll
    for (int nt = 0; nt < 4; nt++) {
        int col = wn*32 + nt*8 + 2*tig;
        float bx = bias[bn0 + col], by = bias[bn0 + col + 1];
        #pragma unroll
        for (int mt = 0; mt < MT; mt++) {
            int r0 = wm*(MTILE/2) + mt*16 + g;
            long base0 = (long)batch*cBatch + (long)(rin + r0)*ldc + bn0 + col;
            long base1 = base0 + (long)8*ldc;
            float c0 = acc[mt][nt][0] + bx, c1 = acc[mt][nt][1] + by;
            float c2 = acc[mt][nt][2] + bx, c3 = acc[mt][nt][3] + by;
            if (relu) { c0=fmaxf(c0,0.f); c1=fmaxf(c1,0.f); c2=fmaxf(c2,0.f); c3=fmaxf(c3,0.f); }
            if (res) {
                float2 r0v = *reinterpret_cast<const float2*>(res + base0);
                float2 r1v = *reinterpret_cast<const float2*>(res + base1);
                c0 += r0v.x; c1 += r0v.y; c2 += r1v.x; c3 += r1v.y;
            }
            if (outBf16) {
                __nv_bfloat162 v0, v1;
                v0.x = __float2bfloat16_rn(c0); v0.y = __float2bfloat16_rn(c1);
                v1.x = __float2bfloat16_rn(c2); v1.y = __float2bfloat16_rn(c3);
                *reinterpret_cast<__nv_bfloat162*>(Cb + base0) = v0;
                *reinterpret_cast<__nv_bfloat162*>(Cb + base1) = v1;
            } else {
                if (roundOut) { c0=rtf32(c0); c1=rtf32(c1); c2=rtf32(c2); c3=rtf32(c3); }
                *reinterpret_cast<float2*>(Cf + base0) = make_float2(c0, c1);
                *reinterpret_cast<float2*>(Cf + base1) = make_float2(c2, c3);
            }
        }
    }
}

// ---------------- per-NS-position linear: vectorized K-split partials ----------------
__global__ __launch_bounds__(128) void ns_split4_kernel(
    const float* __restrict__ X, long xBatch, int xRow,
    const float* __restrict__ W, float* __restrict__ part,
    int K, int N, int kchunk)
{
    __shared__ float Xs[4][512];
    int n = blockIdx.y, z = blockIdx.z;
    int t = threadIdx.x;
    int o4 = (blockIdx.x*128 + t)*4;
    int k0 = z*kchunk;
    for (int i = t; i < kchunk; i += 128) {
        long xo = (long)n*xRow + k0 + i;
        Xs[0][i] = X[0*xBatch + xo];
        Xs[1][i] = X[1*xBatch + xo];
        Xs[2][i] = X[2*xBatch + xo];
        Xs[3][i] = X[3*xBatch + xo];
    }
    __syncthreads();
    const float* Wp = W + (long)n*K*N + (long)k0*N + o4;
    float acc[4][4];
    #pragma unroll
    for (int b = 0; b < 4; b++)
        #pragma unroll
        for (int j = 0; j < 4; j++) acc[b][j] = 0.f;
    #pragma unroll 8
    for (int k = 0; k < kchunk; k++) {
        float4 wv = *reinterpret_cast<const float4*>(Wp + (long)k*N);
        #pragma unroll
        for (int b = 0; b < 4; b++) {
            float xv = Xs[b][k];
            acc[b][0] += xv*wv.x; acc[b][1] += xv*wv.y;
            acc[b][2] += xv*wv.z; acc[b][3] += xv*wv.w;
        }
    }
    #pragma unroll
    for (int b = 0; b < 4; b++)
        *reinterpret_cast<float4*>(&part[((long)(z*BSZ+b)*NSN + n)*N + o4]) =
            make_float4(acc[b][0], acc[b][1], acc[b][2], acc[b][3]);
}

__global__ __launch_bounds__(256) void ns_reduce_kernel(
    const float* __restrict__ part, const float* __restrict__ bias,
    float* __restrict__ Y, long yBatch, int yRow, int N, int KS, int relu, int roundOut,
    const float* __restrict__ res)
{
    int o = blockIdx.x*256 + threadIdx.x;
    int n = blockIdx.y, b = blockIdx.z;
    float s = bias[(long)n*N + o];
    for (int z = 0; z < KS; z++)
        s += part[((long)(z*BSZ+b)*NSN + n)*N + o];
    if (relu) s = fmaxf(s, 0.f);
    if (roundOut) s = rtf32(s);
    long idx = (long)b*yBatch + (long)n*yRow + o;
    if (res) s += res[idx];
    Y[idx] = s;
}

// ---------------- RoPE in-place (fp32 path, rounded output) ----------------
__global__ void rope_kernel(float* __restrict__ buf, int rowsPerB, int pos0, int rstride, int total) {
    int idx = blockIdx.x*blockDim.x + threadIdx.x;
    if (idx >= total) return;
    int j  = idx & 31;
    int h  = (idx >> 5) & (NH-1);
    int rr = idx >> 9;
    int b  = rr / rowsPerB;
    int r  = rr - b*rowsPerB;
    float inv = exp2f(-(float)j * 0.41524101186092029f);
    double ang = (double)(pos0 + r) * (double)inv;
    const double TWO_PI = 6.2831853071795864769;
    double red = ang - TWO_PI * rint(ang * (1.0/6.2831853071795864769));
    float rf = (float)red;
    float s, c;
    sincosf(rf, &s, &c);
    float* base = buf + ((long)b*rowsPerB + r)*(long)rstride + h*HD;
    float x1 = base[j], x2 = base[j+32];
    base[j]    = rtf32(x1*c - x2*s);
    base[j+32] = rtf32(x2*c + x1*s);
}

// ---------------- tf32 flash attention, 64-key tiles, Q hoisted, 3 barriers/tile ----------
#define ATT_QS(r,c)      dsm[(r)*68 + (c)]
#define ATT_KS(bf,r,c)   dsm[4352 + (bf)*4352 + (r)*68 + (c)]
#define ATT_VS(bf,r,c)   dsm[13056 + (bf)*4608 + (r)*72 + (c)]
#define ATT_SS(r,c)      dsm[22272 + (r)*68 + (c)]
#define ATT_SMEM_FLOATS  (26752 + 128)

__global__ __launch_bounds__(256, 2) void attn_mma_kernel(
    const float* __restrict__ q, const float* __restrict__ kv,
    float* __restrict__ attn, const int* __restrict__ seqlen)
{
    extern __shared__ float dsm[];
    float* corrs = dsm + 26752;
    float* lrow  = corrs + 64;

    int qt = blockIdx.x, h = blockIdx.y, b = blockIdx.z;
    int tid = threadIdx.x;
    int w = tid >> 5, lane = tid & 31;
    int g = lane >> 2, tig = lane & 3;
    int wm = w >> 2, wn = w & 3;
    int L = seqlen[b];
    int kmin = MAXS - L;

    for (int i = tid; i < 64*16; i += 256) {
        int r = i >> 4, c4 = (i & 15) * 4;
        int qg = qt*64 + r;
        float4 val = make_float4(0.f,0.f,0.f,0.f);
        if (qg < QLEN)
            val = *reinterpret_cast<const float4*>(q + ((long)b*QLEN + qg)*DM + h*HD + c4);
        *reinterpret_cast<float4*>(&ATT_QS(r, c4)) = val;
    }

    int srow = tid >> 2, ssub = tid & 3;
    float m = -1e30f, l = 0.f;

    float oacc[2][2][4];
    #pragma unroll
    for (int i = 0; i < 2; i++)
        #pragma unroll
        for (int j = 0; j < 2; j++)
            #pragma unroll
            for (int r = 0; r < 4; r++) oacc[i][j][r] = 0.f;

    int qgmax = min(QLEN-1, qt*64 + 63);
    int t0 = kmin >> 6;
    int t1 = (MAXS - OUTN + qgmax) >> 6;

    uint32_t smBase = (uint32_t)__cvta_generic_to_shared(dsm);

    auto loadTile = [&](int kt) {
        int buf = kt & 1;
        int key0 = kt * 64;
        #pragma unroll
        for (int it = 0; it < 4; it++) {
            int i = tid + it*256;
            int r = i >> 4;
            int c4 = (i & 15) * 4;
            int key = key0 + r;
            long off = ((long)b*TOTAL + min(key, TOTAL-1))*(2*DM) + h*HD + c4;
            cpa16(smBase + (4352 + buf*4352 + r*68 + c4)*4, kv + off);
            cpa16(smBase + (13056 + buf*4608 + r*72 + c4)*4, kv + off + DM);
        }
        asm volatile("cp.async.commit_group;");
    };
    loadTile(t0);
    asm volatile("cp.async.commit_group;");

    __syncthreads();
    uint32_t qfr[8][2][4];
    #pragma unroll
    for (int dk = 0; dk < 8; dk++)
        #pragma unroll
        for (int mt = 0; mt < 2; mt++) {
            int m0 = wm*32 + mt*16;
            qfr[dk][mt][0] = f2u(ATT_QS(m0+g,   dk*8+tig));
            qfr[dk][mt][1] = f2u(ATT_QS(m0+g+8, dk*8+tig));
            qfr[dk][mt][2] = f2u(ATT_QS(m0+g,   dk*8+tig+4));
            qfr[dk][mt][3] = f2u(ATT_QS(m0+g+8, dk*8+tig+4));
        }

    for (int kt = t0; kt <= t1; kt++) {
        int key0 = kt * 64;
        int buf = kt & 1;
        asm volatile("cp.async.wait_group 1;");
        __syncthreads();
        if (kt + 1 <= t1) loadTile(kt + 1);
        else              asm volatile("cp.async.commit_group;");

        float sa[2][2][4];
        #pragma unroll
        for (int mt = 0; mt < 2; mt++)
            #pragma unroll
            for (int kn = 0; kn < 2; kn++)
                #pragma unroll
                for (int r = 0; r < 4; r++) sa[mt][kn][r] = 0.f;
        #pragma unroll
        for (int dk = 0; dk < 8; dk++) {
            #pragma unroll
            for (int kn = 0; kn < 2; kn++) {
                uint32_t bf0 = f2u(ATT_KS(buf, wn*16 + kn*8 + g, dk*8 + tig));
                uint32_t bf1 = f2u(ATT_KS(buf, wn*16 + kn*8 + g, dk*8 + tig + 4));
                #pragma unroll
                for (int mt = 0; mt < 2; mt++)
                    mma_tf32(sa[mt][kn], qfr[dk][mt][0], qfr[dk][mt][1],
                             qfr[dk][mt][2], qfr[dk][mt][3], bf0, bf1);
            }
        }
        #pragma unroll
        for (int mt = 0; mt < 2; mt++) {
            #pragma unroll
            for (int kn = 0; kn < 2; kn++) {
                #pragma unroll
                for (int hh = 0; hh < 2; hh++) {
                    int r = wm*32 + mt*16 + g + hh*8;
                    int qg = qt*64 + r;
                    int col = wn*16 + kn*8 + 2*tig;
                    int key = key0 + col;
                    int kcap = MAXS - OUTN + qg;
                    bool rowok = (qg < QLEN);
                    float sA = sa[mt][kn][hh*2+0], sB = sa[mt][kn][hh*2+1];
                    bool v0 = rowok && (key   < TOTAL) && (key   >= kmin) && (key   <= kcap);
                    bool v1 = rowok && (key+1 < TOTAL) && (key+1 >= kmin) && (key+1 <= kcap);
                    ATT_SS(r, col)     = v0 ? sA*0.125f : -1e9f;
                    ATT_SS(r, col + 1) = v1 ? sB*0.125f : -1e9f;
                }
            }
        }
        __syncthreads();

        float sv[16];
        #pragma unroll
        for (int j = 0; j < 16; j++) sv[j] = ATT_SS(srow, ssub*16 + j);
        float tmax = sv[0];
        #pragma unroll
        for (int j = 1; j < 16; j++) tmax = fmaxf(tmax, sv[j]);
        tmax = fmaxf(tmax, __shfl_xor_sync(0xffffffffu, tmax, 1));
        tmax = fmaxf(tmax, __shfl_xor_sync(0xffffffffu, tmax, 2));
        float corr = 1.f;
        if (tmax > -1e8f) {
            float m_new = fmaxf(m, tmax);
            corr = __expf(m - m_new);
            float ps = 0.f;
            #pragma unroll
            for (int j = 0; j < 16; j++) {
                float p = __expf(sv[j] - m_new);
                ps += p;
                ATT_SS(srow, ssub*16 + j) = rtf32(p);
            }
            ps += __shfl_xor_sync(0xffffffffu, ps, 1);
            ps += __shfl_xor_sync(0xffffffffu, ps, 2);
            l = l*corr + ps;
            m = m_new;
        } else {
            #pragma unroll
            for (int j = 0; j < 16; j++) ATT_SS(srow, ssub*16 + j) = 0.f;
        }
        if (ssub == 0) corrs[srow] = corr;
        __syncthreads();

        #pragma unroll
        for (int mt = 0; mt < 2; mt++) {
            float c0 = corrs[wm*32 + mt*16 + g];
            float c1 = corrs[wm*32 + mt*16 + g + 8];
            #pragma unroll
            for (int nt = 0; nt < 2; nt++) {
                oacc[mt][nt][0] *= c0; oacc[mt][nt][1] *= c0;
                oacc[mt][nt][2] *= c1; oacc[mt][nt][3] *= c1;
            }
        }
        #pragma unroll
        for (int kd = 0; kd < 8; kd++) {
            uint32_t bf[2][2];
            #pragma unroll
            for (int nt = 0; nt < 2; nt++) {
                int n = wn*16 + nt*8 + g;
                bf[nt][0] = f2u(ATT_VS(buf, kd*8 + tig,     n));
                bf[nt][1] = f2u(ATT_VS(buf, kd*8 + tig + 4, n));
            }
            #pragma unroll
            for (int mt = 0; mt < 2; mt++) {
                int m0 = wm*32 + mt*16;
                uint32_t a0 = f2u(ATT_SS(m0+g,   kd*8+tig));
                uint32_t a1 = f2u(ATT_SS(m0+g+8, kd*8+tig));
                uint32_t a2 = f2u(ATT_SS(m0+g,   kd*8+tig+4));
                uint32_t a3 = f2u(ATT_SS(m0+g+8, kd*8+tig+4));
                #pragma unroll
                for (int nt = 0; nt < 2; nt++)
                    mma_tf32(oacc[mt][nt], a0, a1, a2, a3, bf[nt][0], bf[nt][1]);
            }
        }
        // no end-of-loop barrier: next iteration's top __syncthreads orders reuse
    }

    if (ssub == 0) lrow[srow] = l;
    __syncthreads();
    #pragma unroll
    for (int mt = 0; mt < 2; mt++) {
        #pragma unroll
        for (int hh = 0; hh < 2; hh++) {
            int r = wm*32 + mt*16 + g + hh*8;
            int qg = qt*64 + r;
            if (qg < QLEN) {
                float invl = 1.f / lrow[r];
                #pragma unroll
                for (int nt = 0; nt < 2; nt++) {
                    int col = wn*16 + nt*8 + 2*tig;
                    *reinterpret_cast<float2*>(attn + ((long)b*QLEN + qg)*DM + h*HD + col)
                        = make_float2(oacc[mt][nt][hh*2]*invl, oacc[mt][nt][hh*2+1]*invl);
                }
            }
        }
    }
}

// ---------------- tail: optional seqlen extras ----------------
__global__ void tail_kernel(float* __restrict__ out, const int* __restrict__ seqlen, int out_size) {
    int b = threadIdx.x;
    const int main_n = BSZ*QLEN*DM;
    if (b < BSZ && out_size >= main_n + BSZ) {
        int L = seqlen[b];
        out[main_n + b] = (float)(L < OUTN ? L : OUTN);
    }
}

extern "C" void kernel_launch(void* const* d_in, const int* in_sizes, int n_in,
                              void* d_out, int out_size) {
    (void)in_sizes; (void)n_in;
    const float* x    = (const float*)d_in[0];
    const int*   seq  = (const int*)  d_in[1];
    const float* wqkv = (const float*)d_in[2];
    const float* bqkv = (const float*)d_in[3];
    const float* wnsq = (const float*)d_in[4];
    const float* bnsq = (const float*)d_in[5];
    const float* wnsk = (const float*)d_in[6];
    const float* bnsk = (const float*)d_in[7];
    const float* wnsv = (const float*)d_in[8];
    const float* bnsv = (const float*)d_in[9];
    const float* n1w  = (const float*)d_in[10];
    const float* n2w  = (const float*)d_in[11];
    const float* fw1  = (const float*)d_in[12];
    const float* fb1  = (const float*)d_in[13];
    const float* fw2  = (const float*)d_in[14];
    const float* fb2  = (const float*)d_in[15];
    const float* w1ns = (const float*)d_in[16];
    const float* b1ns = (const float*)d_in[17];
    const float* w2ns = (const float*)d_in[18];
    const float* b2ns = (const float*)d_in[19];
    float* out = (float*)d_out;

    float *xn,*q,*kv,*attn,*h1,*hn,*tns,*fns,*part;
    __nv_bfloat16 *xnb,*hnb,*tsb,*wqb,*w1b,*w2b;
    cudaGetSymbolAddress((void**)&xn,   g_xn);
    cudaGetSymbolAddress((void**)&q,    g_q);
    cudaGetSymbolAddress((void**)&kv,   g_kv);
    cudaGetSymbolAddress((void**)&attn, g_attn);
    cudaGetSymbolAddress((void**)&h1,   g_h1);
    cudaGetSymbolAddress((void**)&hn,   g_hn);
    cudaGetSymbolAddress((void**)&tns,  g_tns);
    cudaGetSymbolAddress((void**)&fns,  g_fns);
    cudaGetSymbolAddress((void**)&part, g_part);
    cudaGetSymbolAddress((void**)&xnb,  g_xnb);
    cudaGetSymbolAddress((void**)&hnb,  g_hnb);
    cudaGetSymbolAddress((void**)&tsb,  g_tsb);
    cudaGetSymbolAddress((void**)&wqb,  g_wqkvb);
    cudaGetSymbolAddress((void**)&w1b,  g_w1b);
    cudaGetSymbolAddress((void**)&w2b,  g_w2b);
    float* part2 = part + 2*1024*1024;

    const long aB  = (long)TOTAL*DM;
    const long qB  = (long)QLEN*DM;
    const long kvB = (long)TOTAL*2*DM;

    const int SMEMB128 = (3*128*40 + 3*128*40) * 2;   // 61440 B
    const int SMEMB64  = (3*64*40  + 3*128*40) * 2;   // 46080 B
    const int ATTSMEM  = ATT_SMEM_FLOATS * 4;
    cudaFuncSetAttribute(mma_gemmB_kernel<128>, cudaFuncAttributeMaxDynamicSharedMemorySize, SMEMB128);
    cudaFuncSetAttribute(mma_gemmB_kernel<64>,  cudaFuncAttributeMaxDynamicSharedMemorySize, SMEMB64);
    cudaFuncSetAttribute(attn_mma_kernel, cudaFuncAttributeMaxDynamicSharedMemorySize, ATTSMEM);

    static cudaStream_t s1 = nullptr, s2 = nullptr, s3 = nullptr;
    static cudaEvent_t  eB, e0, e1, e2, e2a, e3, e4, e5;
    if (s1 == nullptr) {
        cudaStreamCreateWithFlags(&s1, cudaStreamNonBlocking);
        cudaStreamCreateWithFlags(&s2, cudaStreamNonBlocking);
        cudaStreamCreateWithFlags(&s3, cudaStreamNonBlocking);
        cudaEventCreateWithFlags(&eB,  cudaEventDisableTiming);
        cudaEventCreateWithFlags(&e0,  cudaEventDisableTiming);
        cudaEventCreateWithFlags(&e1,  cudaEventDisableTiming);
        cudaEventCreateWithFlags(&e2,  cudaEventDisableTiming);
        cudaEventCreateWithFlags(&e2a, cudaEventDisableTiming);
        cudaEventCreateWithFlags(&e3,  cudaEventDisableTiming);
        cudaEventCreateWithFlags(&e4,  cudaEventDisableTiming);
        cudaEventCreateWithFlags(&e5,  cudaEventDisableTiming);
    }
    cudaStream_t s0 = 0;

    // ---- Phase 1 : rmsnorm (s0) || weight transposes (s2) ----
    cudaEventRecord(eB, s0);
    cudaStreamWaitEvent(s2, eB, 0);
    transpose_bf16_kernel<<<dim3(3*DM/32, DM/32), dim3(32,8), 0, s2>>>(wqkv, wqb, DM, 3*DM);
    cudaEventRecord(e2a, s2);
    transpose_bf16_kernel<<<dim3(FFND/32, DM/32), dim3(32,8), 0, s2>>>(fw1, w1b, DM, FFND);
    transpose_bf16_kernel<<<dim3(DM/32, FFND/32), dim3(32,8), 0, s2>>>(fw2, w2b, FFND, DM);
    cudaEventRecord(e2, s2);

    rmsnorm_kernel<<<BSZ*TOTAL, 256, 0, s0>>>(x, n1w, xn, xnb);
    cudaEventRecord(e0, s0);

    // s1: Q projection -> ns_q -> rope_q
    cudaStreamWaitEvent(s1, e0, 0);
    cudaStreamWaitEvent(s1, e2a, 0);
    mma_gemmB_kernel<64><<<dim3(DM/128, (BSZ*OUTN)/64), 256, SMEMB64, s1>>>(
        xnb + (long)(MAXS-OUTN)*DM, DM, aB, OUTN, wqb, DM, bqkv, q, DM, qB, DM, 0, 1, 0, seq, 0, nullptr);
    ns_split4_kernel<<<dim3(DM/512, NSN, 32), 128, 0, s1>>>(xn + (long)MAXS*DM, aB, DM, wnsq, part2, DM, DM, DM/32);
    ns_reduce_kernel<<<dim3(DM/256, NSN, BSZ), 256, 0, s1>>>(part2, bnsq, q + (long)OUTN*DM, qB, DM, DM, 32, 0, 1, nullptr);
    {
        int totq = BSZ*QLEN*NH*32;
        rope_kernel<<<(totq+255)/256, 256, 0, s1>>>(q, QLEN, TOTAL-QLEN, DM, totq);
    }
    cudaEventRecord(e1, s1);

    // s3: ns_v then ns_k
    cudaStreamWaitEvent(s3, e0, 0);
    ns_split4_kernel<<<dim3(DM/512, NSN, 32), 128, 0, s3>>>(xn + (long)MAXS*DM, aB, DM, wnsv, part, DM, DM, DM/32);
    ns_reduce_kernel<<<dim3(DM/256, NSN, BSZ), 256, 0, s3>>>(part, bnsv, kv + (long)MAXS*2*DM + DM, kvB, 2*DM, DM, 32, 0, 1, nullptr);
    ns_split4_kernel<<<dim3(DM/512, NSN, 32), 128, 0, s3>>>(xn + (long)MAXS*DM, aB, DM, wnsk, part, DM, DM, DM/32);
    ns_reduce_kernel<<<dim3(DM/256, NSN, BSZ), 256, 0, s3>>>(part, bnsk, kv + (long)MAXS*2*DM, kvB, 2*DM, DM, 32, 0, 1, nullptr);
    cudaEventRecord(e3, s3);

    // s0: KV projection, then rope_k
    cudaStreamWaitEvent(s0, e2a, 0);
    mma_gemmB_kernel<128><<<dim3(2*DM/128, (BSZ*MAXS)/128), 256, SMEMB128, s0>>>(xnb, DM, aB, MAXS,
        wqb + (long)DM*DM, DM, bqkv + DM, kv, 2*DM, kvB, DM, 0, 1, 0, seq, 1, nullptr);
    cudaStreamWaitEvent(s0, e3, 0);
    {
        int totk = BSZ*TOTAL*NH*32;
        rope_kernel<<<(totk+255)/256, 256, 0, s0>>>(kv, TOTAL, 0, 2*DM, totk);
    }

    cudaStreamWaitEvent(s0, e1, 0);
    attn_mma_kernel<<<dim3((QLEN+63)/64, NH, BSZ), 256, ATTSMEM, s0>>>(q, kv, attn, seq);

    add_rmsnorm_kernel<<<BSZ*QLEN, 256, 0, s0>>>(x, n2w);
    cudaEventRecord(e4, s0);

    // ---- Phase 2 ----
    cudaStreamWaitEvent(s1, e4, 0);
    ns_split4_kernel<<<dim3(FFND/512, NSN, 16), 128, 0, s1>>>(hn + (long)OUTN*DM, qB, DM, w1ns, part, DM, FFND, DM/16);
    ns_reduce_kernel<<<dim3(FFND/256, NSN, BSZ), 256, 0, s1>>>(part, b1ns, tns, (long)NSN*FFND, FFND, FFND, 16, 1, 0, nullptr);
    ns_split4_kernel<<<dim3(DM/512, NSN, 32), 128, 0, s1>>>(tns, (long)NSN*FFND, FFND, w2ns, part, FFND, DM, FFND/32);
    ns_reduce_kernel<<<dim3(DM/256, NSN, BSZ), 256, 0, s1>>>(part, b2ns,
        out + (long)OUTN*DM, qB, DM, DM, 32, 0, 0, h1 + (long)OUTN*DM);
    cudaEventRecord(e5, s1);

    cudaStreamWaitEvent(s0, e2, 0);
    mma_gemmB_kernel<128><<<dim3(FFND/128, (BSZ*OUTN)/128), 256, SMEMB128, s0>>>(hnb, DM, qB, OUTN,
        w1b, DM, fb1, tsb, FFND, (long)OUTN*FFND, DM, 1, 0, 1, seq, 0, nullptr);
    mma_gemmB_kernel<64><<<dim3(DM/128, (BSZ*OUTN)/64), 256, SMEMB64, s0>>>(tsb, FFND, (long)OUTN*FFND, OUTN,
        w2b, FFND, fb2, out, DM, qB, FFND, 0, 0, 0, seq, 0, h1);

    cudaStreamWaitEvent(s0, e5, 0);
    tail_kernel<<<1, BSZ, 0, s0>>>(out, seq, out_size);
}

// round 17
// speedup vs baseline: 1.0913x; 1.0414x over previous
#include <cuda_runtime.h>
#include <cuda_bf16.h>
#include <cstdint>

#define BSZ   4
#define TOTAL 2064
#define DM    1024
#define NSN   16
#define OUTN  256
#define QLEN  272
#define NH    16
#define HD    64
#define FFND  4096
#define MAXS  2048

// Scratch (static device globals; no allocation allowed)
__device__ float g_xn  [BSZ*TOTAL*DM];
__device__ float g_q   [BSZ*QLEN*DM];
__device__ float g_kv  [BSZ*TOTAL*2*DM];
__device__ float g_attn[BSZ*QLEN*DM];
__device__ float g_h1  [BSZ*QLEN*DM];
__device__ float g_hn  [BSZ*QLEN*DM];
__device__ float g_tns [BSZ*NSN*FFND];
__device__ float g_fns [BSZ*NSN*DM];
__device__ float g_part[4*1024*1024];
// bf16 activations + transposed bf16 weights ([N,K] row-major)
__device__ __nv_bfloat16 g_xnb [BSZ*TOTAL*DM];
__device__ __nv_bfloat16 g_hnb [BSZ*QLEN*DM];
__device__ __nv_bfloat16 g_tsb [BSZ*OUTN*FFND];
__device__ __nv_bfloat16 g_wqkvb[3*DM*DM];
__device__ __nv_bfloat16 g_w1b  [FFND*DM];
__device__ __nv_bfloat16 g_w2b  [DM*FFND];

__device__ __forceinline__ float rtf32(float x) {
    uint32_t u;
    asm("cvt.rna.tf32.f32 %0, %1;" : "=r"(u) : "f"(x));
    return __uint_as_float(u);
}
__device__ __forceinline__ uint32_t f2u(float x) { return __float_as_uint(x); }

__device__ __forceinline__ void cpa16(uint32_t dst, const void* src) {
    asm volatile("cp.async.ca.shared.global [%0], [%1], 16;" :: "r"(dst), "l"(src));
}

__device__ __forceinline__ void mma_tf32(float* c,
        uint32_t a0, uint32_t a1, uint32_t a2, uint32_t a3,
        uint32_t b0, uint32_t b1) {
    asm volatile(
        "mma.sync.aligned.m16n8k8.row.col.f32.tf32.tf32.f32 "
        "{%0,%1,%2,%3}, {%4,%5,%6,%7}, {%8,%9}, {%0,%1,%2,%3};\n"
        : "+f"(c[0]), "+f"(c[1]), "+f"(c[2]), "+f"(c[3])
        : "r"(a0), "r"(a1), "r"(a2), "r"(a3), "r"(b0), "r"(b1));
}
__device__ __forceinline__ void mma_bf16(float* c,
        uint32_t a0, uint32_t a1, uint32_t a2, uint32_t a3,
        uint32_t b0, uint32_t b1) {
    asm volatile(
        "mma.sync.aligned.m16n8k16.row.col.f32.bf16.bf16.f32 "
        "{%0,%1,%2,%3}, {%4,%5,%6,%7}, {%8,%9}, {%0,%1,%2,%3};\n"
        : "+f"(c[0]), "+f"(c[1]), "+f"(c[2]), "+f"(c[3])
        : "r"(a0), "r"(a1), "r"(a2), "r"(a3), "r"(b0), "r"(b1));
}

__device__ __forceinline__ void ldsm4(uint32_t* r, uint32_t addr) {
    asm volatile("ldmatrix.sync.aligned.m8n8.x4.shared.b16 {%0,%1,%2,%3}, [%4];"
        : "=r"(r[0]), "=r"(r[1]), "=r"(r[2]), "=r"(r[3]) : "r"(addr));
}

// ---------------- transpose + bf16 convert ----------------
__global__ __launch_bounds__(256) void transpose_bf16_kernel(const float* __restrict__ in,
        __nv_bfloat16* __restrict__ out, int R, int C) {
    __shared__ float tile[32][33];
    int c0 = blockIdx.x*32, r0 = blockIdx.y*32;
    int tx = threadIdx.x, ty = threadIdx.y;
    for (int i = ty; i < 32; i += 8)
        tile[i][tx] = in[(long)(r0+i)*C + c0 + tx];
    __syncthreads();
    for (int i = ty; i < 32; i += 8)
        out[(long)(c0+i)*R + r0 + tx] = __float2bfloat16_rn(tile[tx][i]);
}

// ---------------- rmsnorm: fp32 (tf32-rounded) + bf16 outputs ----------------
__global__ __launch_bounds__(256) void rmsnorm_kernel(const float* __restrict__ in,
        const float* __restrict__ w, float* __restrict__ outf,
        __nv_bfloat16* __restrict__ outb) {
    long row = blockIdx.x;
    int t = threadIdx.x;
    float4 v = reinterpret_cast<const float4*>(in + row*DM)[t];
    float ss = v.x*v.x + v.y*v.y + v.z*v.z + v.w*v.w;
    __shared__ float red[8];
    for (int o = 16; o; o >>= 1) ss += __shfl_xor_sync(0xffffffffu, ss, o);
    if ((t & 31) == 0) red[t >> 5] = ss;
    __syncthreads();
    if (t < 32) {
        float s = (t < 8) ? red[t] : 0.f;
        for (int o = 4; o; o >>= 1) s += __shfl_xor_sync(0xffffffffu, s, o);
        if (t == 0) red[0] = s;
    }
    __syncthreads();
    float rs = rsqrtf(red[0] * (1.f/DM) + 1e-6f);
    float4 wv = reinterpret_cast<const float4*>(w)[t];
    float p0 = v.x*rs*wv.x, p1 = v.y*rs*wv.y, p2 = v.z*rs*wv.z, p3 = v.w*rs*wv.w;
    reinterpret_cast<float4*>(outf + row*DM)[t] =
        make_float4(rtf32(p0), rtf32(p1), rtf32(p2), rtf32(p3));
    __nv_bfloat162 b01, b23;
    b01.x = __float2bfloat16_rn(p0); b01.y = __float2bfloat16_rn(p1);
    b23.x = __float2bfloat16_rn(p2); b23.y = __float2bfloat16_rn(p3);
    reinterpret_cast<__nv_bfloat162*>(outb + row*DM)[t*2]   = b01;
    reinterpret_cast<__nv_bfloat162*>(outb + row*DM)[t*2+1] = b23;
}

// ---------------- h1 = x + attn ; hn (fp32 + bf16) ----------------
__global__ __launch_bounds__(256) void add_rmsnorm_kernel(const float* __restrict__ x,
        const float* __restrict__ w) {
    int row = blockIdx.x;
    int b = row / QLEN, r = row - b*QLEN;
    int t = threadIdx.x;
    float4 xv = reinterpret_cast<const float4*>(x + ((long)b*TOTAL + (TOTAL-QLEN) + r)*DM)[t];
    float4 av = reinterpret_cast<const float4*>(g_attn + (long)row*DM)[t];
    float4 hv = make_float4(xv.x+av.x, xv.y+av.y, xv.z+av.z, xv.w+av.w);
    reinterpret_cast<float4*>(g_h1 + (long)row*DM)[t] = hv;
    float ss = hv.x*hv.x + hv.y*hv.y + hv.z*hv.z + hv.w*hv.w;
    __shared__ float red[8];
    for (int o = 16; o; o >>= 1) ss += __shfl_xor_sync(0xffffffffu, ss, o);
    if ((t & 31) == 0) red[t >> 5] = ss;
    __syncthreads();
    if (t < 32) {
        float s = (t < 8) ? red[t] : 0.f;
        for (int o = 4; o; o >>= 1) s += __shfl_xor_sync(0xffffffffu, s, o);
        if (t == 0) red[0] = s;
    }
    __syncthreads();
    float rs = rsqrtf(red[0] * (1.f/DM) + 1e-6f);
    float4 wv = reinterpret_cast<const float4*>(w)[t];
    float p0 = hv.x*rs*wv.x, p1 = hv.y*rs*wv.y, p2 = hv.z*rs*wv.z, p3 = hv.w*rs*wv.w;
    reinterpret_cast<float4*>(g_hn + (long)row*DM)[t] =
        make_float4(rtf32(p0), rtf32(p1), rtf32(p2), rtf32(p3));
    __nv_bfloat162 b01, b23;
    b01.x = __float2bfloat16_rn(p0); b01.y = __float2bfloat16_rn(p1);
    b23.x = __float2bfloat16_rn(p2); b23.y = __float2bfloat16_rn(p3);
    reinterpret_cast<__nv_bfloat162*>(g_hnb + (long)row*DM)[t*2]   = b01;
    reinterpret_cast<__nv_bfloat162*>(g_hnb + (long)row*DM)[t*2+1] = b23;
}

// ---------------- BF16 tensor-core GEMM, MTILEx128x32, 3-stage cp.async ----------
template<int MTILE>
__global__ __launch_bounds__(256, 2) void mma_gemmB_kernel(
    const __nv_bfloat16* __restrict__ A, int lda, long aBatch, int rpb,
    const __nv_bfloat16* __restrict__ Bt, int ldbt,
    const float* __restrict__ bias,
    void* __restrict__ Cv, int ldc, long cBatch,
    int K, int relu, int roundOut, int outBf16,
    const int* __restrict__ seqlen, int kvSkip,
    const float* __restrict__ res)
{
    constexpr int S    = 3;
    constexpr int PAD  = 40;
    constexpr int ASTG = MTILE*PAD;
    constexpr int BSTG = 128*PAD;
    constexpr int MT   = MTILE/32;
    extern __shared__ __nv_bfloat16 smb[];
    __nv_bfloat16* AsBase = smb;
    __nv_bfloat16* BsBase = smb + S*ASTG;

    int t = threadIdx.x;
    int w = t >> 5, lane = t & 31;
    int g = lane >> 2, tig = lane & 3;
    int wm = w >> 2, wn = w & 3;

    int row0 = blockIdx.y * MTILE;
    int bn0  = blockIdx.x * 128;
    int batch = row0 / rpb;
    int rin   = row0 % rpb;
    if (kvSkip) {
        int kmin = MAXS - seqlen[batch];
        if (rin + MTILE - 1 < kmin) return;
    }
    const __nv_bfloat16* Ab = A + (long)batch*aBatch + (long)rin*lda;
    const __nv_bfloat16* Bb = Bt + (long)bn0*ldbt;

    uint32_t aSm0 = (uint32_t)__cvta_generic_to_shared(AsBase);
    uint32_t bSm0 = (uint32_t)__cvta_generic_to_shared(BsBase);

    float acc[MT][4][4];
    #pragma unroll
    for (int i = 0; i < MT; i++)
        #pragma unroll
        for (int j = 0; j < 4; j++)
            #pragma unroll
            for (int r = 0; r < 4; r++) acc[i][j][r] = 0.f;

    const int KT = K >> 5;
    auto issue = [&](int kt) {
        int s = kt % S;
        const __nv_bfloat16* ga = Ab + kt*32;
        const __nv_bfloat16* gb = Bb + kt*32;
        uint32_t aS = aSm0 + s*ASTG*2;
        uint32_t bS = bSm0 + s*BSTG*2;
        #pragma unroll
        for (int it = 0; it < MTILE/64; it++) {
            int i = t + it*256;
            int row = i >> 2, seg = i & 3;
            cpa16(aS + (row*PAD + seg*8)*2, ga + (long)row*lda + seg*8);
        }
        #pragma unroll
        for (int it = 0; it < 2; it++) {
            int i = t + it*256;
            int row = i >> 2, seg = i & 3;
            cpa16(bS + (row*PAD + seg*8)*2, gb + (long)row*ldbt + seg*8);
        }
        asm volatile("cp.async.commit_group;");
    };
    issue(0);
    issue(1);

    int aRow  = lane & 15;
    int aColH = (lane >> 4) * 8;
    int bRowO = ((lane >> 4) & 1)*8 + (lane & 7);
    int bColH = ((lane >> 3) & 1)*8;

    for (int kt = 0; kt < KT; kt++) {
        if (kt == KT - 1) asm volatile("cp.async.wait_group 0;");
        else              asm volatile("cp.async.wait_group 1;");
        __syncthreads();
        if (kt + 2 < KT) issue(kt + 2);

        int s = kt % S;
        uint32_t As = aSm0 + s*ASTG*2;
        uint32_t Bs = bSm0 + s*BSTG*2;
        #pragma unroll
        for (int ks = 0; ks < 2; ks++) {
            uint32_t afr[MT][4];
            #pragma unroll
            for (int mt = 0; mt < MT; mt++)
                ldsm4(afr[mt], As + ((wm*(MTILE/2) + mt*16 + aRow)*PAD + ks*16 + aColH)*2);
            uint32_t bfr[4][2];
            #pragma unroll
            for (int p = 0; p < 2; p++) {
                uint32_t r4[4];
                ldsm4(r4, Bs + ((wn*32 + p*16 + bRowO)*PAD + ks*16 + bColH)*2);
                bfr[2*p][0]   = r4[0]; bfr[2*p][1]   = r4[1];
                bfr[2*p+1][0] = r4[2]; bfr[2*p+1][1] = r4[3];
            }
            #pragma unroll
            for (int mt = 0; mt < MT; mt++)
                #pragma unroll
                for (int nt = 0; nt < 4; nt++)
                    mma_bf16(acc[mt][nt], afr[mt][0], afr[mt][1], afr[mt][2], afr[mt][3],
                             bfr[nt][0], bfr[nt][1]);
        }
    }

    float* Cf = (float*)Cv;
    __nv_bfloat16* Cb = (__nv_bfloat16*)Cv;
    #pragma unroll
    for (int nt = 0; nt < 4; nt++) {
        int col = wn*32 + nt*8 + 2*tig;
        float bx = bias[bn0 + col], by = bias[bn0 + col + 1];
        #pragma unroll
        for (int mt = 0; mt < MT; mt++) {
            int r0 = wm*(MTILE/2) + mt*16 + g;
            long base0 = (long)batch*cBatch + (long)(rin + r0)*ldc + bn0 + col;
            long base1 = base0 + (long)8*ldc;
            float c0 = acc[mt][nt][0] + bx, c1 = acc[mt][nt][1] + by;
            float c2 = acc[mt][nt][2] + bx, c3 = acc[mt][nt][3] + by;
            if (relu) { c0=fmaxf(c0,0.f); c1=fmaxf(c1,0.f); c2=fmaxf(c2,0.f); c3=fmaxf(c3,0.f); }
            if (res) {
                float2 r0v = *reinterpret_cast<const float2*>(res + base0);
                float2 r1v = *reinterpret_cast<const float2*>(res + base1);
                c0 += r0v.x; c1 += r0v.y; c2 += r1v.x; c3 += r1v.y;
            }
            if (outBf16) {
                __nv_bfloat162 v0, v1;
                v0.x = __float2bfloat16_rn(c0); v0.y = __float2bfloat16_rn(c1);
                v1.x = __float2bfloat16_rn(c2); v1.y = __float2bfloat16_rn(c3);
                *reinterpret_cast<__nv_bfloat162*>(Cb + base0) = v0;
                *reinterpret_cast<__nv_bfloat162*>(Cb + base1) = v1;
            } else {
                if (roundOut) { c0=rtf32(c0); c1=rtf32(c1); c2=rtf32(c2); c3=rtf32(c3); }
                *reinterpret_cast<float2*>(Cf + base0) = make_float2(c0, c1);
                *reinterpret_cast<float2*>(Cf + base1) = make_float2(c2, c3);
            }
        }
    }
}

// ---------------- per-NS-position linear: vectorized K-split partials ----------------
__global__ __launch_bounds__(128) void ns_split4_kernel(
    const float* __restrict__ X, long xBatch, int xRow,
    const float* __restrict__ W, float* __restrict__ part,
    int K, int N, int kchunk)
{
    __shared__ float Xs[4][512];
    int n = blockIdx.y, z = blockIdx.z;
    int t = threadIdx.x;
    int o4 = (blockIdx.x*128 + t)*4;
    int k0 = z*kchunk;
    for (int i = t; i < kchunk; i += 128) {
        long xo = (long)n*xRow + k0 + i;
        Xs[0][i] = X[0*xBatch + xo];
        Xs[1][i] = X[1*xBatch + xo];
        Xs[2][i] = X[2*xBatch + xo];
        Xs[3][i] = X[3*xBatch + xo];
    }
    __syncthreads();
    const float* Wp = W + (long)n*K*N + (long)k0*N + o4;
    float acc[4][4];
    #pragma unroll
    for (int b = 0; b < 4; b++)
        #pragma unroll
        for (int j = 0; j < 4; j++) acc[b][j] = 0.f;
    #pragma unroll 8
    for (int k = 0; k < kchunk; k++) {
        float4 wv = *reinterpret_cast<const float4*>(Wp + (long)k*N);
        #pragma unroll
        for (int b = 0; b < 4; b++) {
            float xv = Xs[b][k];
            acc[b][0] += xv*wv.x; acc[b][1] += xv*wv.y;
            acc[b][2] += xv*wv.z; acc[b][3] += xv*wv.w;
        }
    }
    #pragma unroll
    for (int b = 0; b < 4; b++)
        *reinterpret_cast<float4*>(&part[((long)(z*BSZ+b)*NSN + n)*N + o4]) =
            make_float4(acc[b][0], acc[b][1], acc[b][2], acc[b][3]);
}

__global__ __launch_bounds__(256) void ns_reduce_kernel(
    const float* __restrict__ part, const float* __restrict__ bias,
    float* __restrict__ Y, long yBatch, int yRow, int N, int KS, int relu, int roundOut,
    const float* __restrict__ res)
{
    int o = blockIdx.x*256 + threadIdx.x;
    int n = blockIdx.y, b = blockIdx.z;
    float s = bias[(long)n*N + o];
    for (int z = 0; z < KS; z++)
        s += part[((long)(z*BSZ+b)*NSN + n)*N + o];
    if (relu) s = fmaxf(s, 0.f);
    if (roundOut) s = rtf32(s);
    long idx = (long)b*yBatch + (long)n*yRow + o;
    if (res) s += res[idx];
    Y[idx] = s;
}

// ---------------- RoPE in-place (fp32 path, rounded output, dead-row skip) ------------
__global__ void rope_kernel(float* __restrict__ buf, int rowsPerB, int pos0, int rstride,
                            int total, const int* __restrict__ seqlen, int skipDead) {
    int idx = blockIdx.x*blockDim.x + threadIdx.x;
    if (idx >= total) return;
    int j  = idx & 31;
    int h  = (idx >> 5) & (NH-1);
    int rr = idx >> 9;
    int b  = rr / rowsPerB;
    int r  = rr - b*rowsPerB;
    // Dead KV rows (r < kmin) feed only masked score lanes (p == 0 exactly);
    // skipping their rotation is bit-identical.
    if (skipDead && r < MAXS - seqlen[b]) return;
    float inv = exp2f(-(float)j * 0.41524101186092029f);
    double ang = (double)(pos0 + r) * (double)inv;
    const double TWO_PI = 6.2831853071795864769;
    double red = ang - TWO_PI * rint(ang * (1.0/6.2831853071795864769));
    float rf = (float)red;
    float s, c;
    sincosf(rf, &s, &c);
    float* base = buf + ((long)b*rowsPerB + r)*(long)rstride + h*HD;
    float x1 = base[j], x2 = base[j+32];
    base[j]    = rtf32(x1*c - x2*s);
    base[j+32] = rtf32(x2*c + x1*s);
}

// ---------------- tf32 flash attention, 64-key tiles, Q hoisted, 3 barriers/tile ----------
#define ATT_QS(r,c)      dsm[(r)*68 + (c)]
#define ATT_KS(bf,r,c)   dsm[4352 + (bf)*4352 + (r)*68 + (c)]
#define ATT_VS(bf,r,c)   dsm[13056 + (bf)*4608 + (r)*72 + (c)]
#define ATT_SS(r,c)      dsm[22272 + (r)*68 + (c)]
#define ATT_SMEM_FLOATS  (26752 + 128)

__global__ __launch_bounds__(256, 2) void attn_mma_kernel(
    const float* __restrict__ q, const float* __restrict__ kv,
    float* __restrict__ attn, const int* __restrict__ seqlen)
{
    extern __shared__ float dsm[];
    float* corrs = dsm + 26752;
    float* lrow  = corrs + 64;

    int qt = blockIdx.x, h = blockIdx.y, b = blockIdx.z;
    int tid = threadIdx.x;
    int w = tid >> 5, lane = tid & 31;
    int g = lane >> 2, tig = lane & 3;
    int wm = w >> 2, wn = w & 3;
    int L = seqlen[b];
    int kmin = MAXS - L;

    for (int i = tid; i < 64*16; i += 256) {
        int r = i >> 4, c4 = (i & 15) * 4;
        int qg = qt*64 + r;
        float4 val = make_float4(0.f,0.f,0.f,0.f);
        if (qg < QLEN)
            val = *reinterpret_cast<const float4*>(q + ((long)b*QLEN + qg)*DM + h*HD + c4);
        *reinterpret_cast<float4*>(&ATT_QS(r, c4)) = val;
    }

    int srow = tid >> 2, ssub = tid & 3;
    float m = -1e30f, l = 0.f;

    float oacc[2][2][4];
    #pragma unroll
    for (int i = 0; i < 2; i++)
        #pragma unroll
        for (int j = 0; j < 2; j++)
            #pragma unroll
            for (int r = 0; r < 4; r++) oacc[i][j][r] = 0.f;

    int qgmax = min(QLEN-1, qt*64 + 63);
    int t0 = kmin >> 6;
    int t1 = (MAXS - OUTN + qgmax) >> 6;

    uint32_t smBase = (uint32_t)__cvta_generic_to_shared(dsm);

    auto loadTile = [&](int kt) {
        int buf = kt & 1;
        int key0 = kt * 64;
        #pragma unroll
        for (int it = 0; it < 4; it++) {
            int i = tid + it*256;
            int r = i >> 4;
            int c4 = (i & 15) * 4;
            int key = key0 + r;
            long off = ((long)b*TOTAL + min(key, TOTAL-1))*(2*DM) + h*HD + c4;
            cpa16(smBase + (4352 + buf*4352 + r*68 + c4)*4, kv + off);
            cpa16(smBase + (13056 + buf*4608 + r*72 + c4)*4, kv + off + DM);
        }
        asm volatile("cp.async.commit_group;");
    };
    loadTile(t0);
    asm volatile("cp.async.commit_group;");

    __syncthreads();
    uint32_t qfr[8][2][4];
    #pragma unroll
    for (int dk = 0; dk < 8; dk++)
        #pragma unroll
        for (int mt = 0; mt < 2; mt++) {
            int m0 = wm*32 + mt*16;
            qfr[dk][mt][0] = f2u(ATT_QS(m0+g,   dk*8+tig));
            qfr[dk][mt][1] = f2u(ATT_QS(m0+g+8, dk*8+tig));
            qfr[dk][mt][2] = f2u(ATT_QS(m0+g,   dk*8+tig+4));
            qfr[dk][mt][3] = f2u(ATT_QS(m0+g+8, dk*8+tig+4));
        }

    for (int kt = t0; kt <= t1; kt++) {
        int key0 = kt * 64;
        int buf = kt & 1;
        asm volatile("cp.async.wait_group 1;");
        __syncthreads();
        if (kt + 1 <= t1) loadTile(kt + 1);
        else              asm volatile("cp.async.commit_group;");

        float sa[2][2][4];
        #pragma unroll
        for (int mt = 0; mt < 2; mt++)
            #pragma unroll
            for (int kn = 0; kn < 2; kn++)
                #pragma unroll
                for (int r = 0; r < 4; r++) sa[mt][kn][r] = 0.f;
        #pragma unroll
        for (int dk = 0; dk < 8; dk++) {
            #pragma unroll
            for (int kn = 0; kn < 2; kn++) {
                uint32_t bf0 = f2u(ATT_KS(buf, wn*16 + kn*8 + g, dk*8 + tig));
                uint32_t bf1 = f2u(ATT_KS(buf, wn*16 + kn*8 + g, dk*8 + tig + 4));
                #pragma unroll
                for (int mt = 0; mt < 2; mt++)
                    mma_tf32(sa[mt][kn], qfr[dk][mt][0], qfr[dk][mt][1],
                             qfr[dk][mt][2], qfr[dk][mt][3], bf0, bf1);
            }
        }
        #pragma unroll
        for (int mt = 0; mt < 2; mt++) {
            #pragma unroll
            for (int kn = 0; kn < 2; kn++) {
                #pragma unroll
                for (int hh = 0; hh < 2; hh++) {
                    int r = wm*32 + mt*16 + g + hh*8;
                    int qg = qt*64 + r;
                    int col = wn*16 + kn*8 + 2*tig;
                    int key = key0 + col;
                    int kcap = MAXS - OUTN + qg;
                    bool rowok = (qg < QLEN);
                    float sA = sa[mt][kn][hh*2+0], sB = sa[mt][kn][hh*2+1];
                    bool v0 = rowok && (key   < TOTAL) && (key   >= kmin) && (key   <= kcap);
                    bool v1 = rowok && (key+1 < TOTAL) && (key+1 >= kmin) && (key+1 <= kcap);
                    ATT_SS(r, col)     = v0 ? sA*0.125f : -1e9f;
                    ATT_SS(r, col + 1) = v1 ? sB*0.125f : -1e9f;
                }
            }
        }
        __syncthreads();

        float sv[16];
        #pragma unroll
        for (int j = 0; j < 16; j++) sv[j] = ATT_SS(srow, ssub*16 + j);
        float tmax = sv[0];
        #pragma unroll
        for (int j = 1; j < 16; j++) tmax = fmaxf(tmax, sv[j]);
        tmax = fmaxf(tmax, __shfl_xor_sync(0xffffffffu, tmax, 1));
        tmax = fmaxf(tmax, __shfl_xor_sync(0xffffffffu, tmax, 2));
        float corr = 1.f;
        if (tmax > -1e8f) {
            float m_new = fmaxf(m, tmax);
            corr = __expf(m - m_new);
            float ps = 0.f;
            #pragma unroll
            for (int j = 0; j < 16; j++) {
                float p = __expf(sv[j] - m_new);
                ps += p;
                ATT_SS(srow, ssub*16 + j) = rtf32(p);
            }
            ps += __shfl_xor_sync(0xffffffffu, ps, 1);
            ps += __shfl_xor_sync(0xffffffffu, ps, 2);
            l = l*corr + ps;
            m = m_new;
        } else {
            #pragma unroll
            for (int j = 0; j < 16; j++) ATT_SS(srow, ssub*16 + j) = 0.f;
        }
        if (ssub == 0) corrs[srow] = corr;
        __syncthreads();

        #pragma unroll
        for (int mt = 0; mt < 2; mt++) {
            float c0 = corrs[wm*32 + mt*16 + g];
            float c1 = corrs[wm*32 + mt*16 + g + 8];
            #pragma unroll
            for (int nt = 0; nt < 2; nt++) {
                oacc[mt][nt][0] *= c0; oacc[mt][nt][1] *= c0;
                oacc[mt][nt][2] *= c1; oacc[mt][nt][3] *= c1;
            }
        }
        #pragma unroll
        for (int kd = 0; kd < 8; kd++) {
            uint32_t bf[2][2];
            #pragma unroll
            for (int nt = 0; nt < 2; nt++) {
                int n = wn*16 + nt*8 + g;
                bf[nt][0] = f2u(ATT_VS(buf, kd*8 + tig,     n));
                bf[nt][1] = f2u(ATT_VS(buf, kd*8 + tig + 4, n));
            }
            #pragma unroll
            for (int mt = 0; mt < 2; mt++) {
                int m0 = wm*32 + mt*16;
                uint32_t a0 = f2u(ATT_SS(m0+g,   kd*8+tig));
                uint32_t a1 = f2u(ATT_SS(m0+g+8, kd*8+tig));
                uint32_t a2 = f2u(ATT_SS(m0+g,   kd*8+tig+4));
                uint32_t a3 = f2u(ATT_SS(m0+g+8, kd*8+tig+4));
                #pragma unroll
                for (int nt = 0; nt < 2; nt++)
                    mma_tf32(oacc[mt][nt], a0, a1, a2, a3, bf[nt][0], bf[nt][1]);
            }
        }
        // no end-of-loop barrier: next iteration's top __syncthreads orders reuse
    }

    if (ssub == 0) lrow[srow] = l;
    __syncthreads();
    #pragma unroll
    for (int mt = 0; mt < 2; mt++) {
        #pragma unroll
        for (int hh = 0; hh < 2; hh++) {
            int r = wm*32 + mt*16 + g + hh*8;
            int qg = qt*64 + r;
            if (qg < QLEN) {
                float invl = 1.f / lrow[r];
                #pragma unroll
                for (int nt = 0; nt < 2; nt++) {
                    int col = wn*16 + nt*8 + 2*tig;
                    *reinterpret_cast<float2*>(attn + ((long)b*QLEN + qg)*DM + h*HD + col)
                        = make_float2(oacc[mt][nt][hh*2]*invl, oacc[mt][nt][hh*2+1]*invl);
                }
            }
        }
    }
}

// ---------------- tail: optional seqlen extras ----------------
__global__ void tail_kernel(float* __restrict__ out, const int* __restrict__ seqlen, int out_size) {
    int b = threadIdx.x;
    const int main_n = BSZ*QLEN*DM;
    if (b < BSZ && out_size >= main_n + BSZ) {
        int L = seqlen[b];
        out[main_n + b] = (float)(L < OUTN ? L : OUTN);
    }
}

extern "C" void kernel_launch(void* const* d_in, const int* in_sizes, int n_in,
                              void* d_out, int out_size) {
    (void)in_sizes; (void)n_in;
    const float* x    = (const float*)d_in[0];
    const int*   seq  = (const int*)  d_in[1];
    const float* wqkv = (const float*)d_in[2];
    const float* bqkv = (const float*)d_in[3];
    const float* wnsq = (const float*)d_in[4];
    const float* bnsq = (const float*)d_in[5];
    const float* wnsk = (const float*)d_in[6];
    const float* bnsk = (const float*)d_in[7];
    const float* wnsv = (const float*)d_in[8];
    const float* bnsv = (const float*)d_in[9];
    const float* n1w  = (const float*)d_in[10];
    const float* n2w  = (const float*)d_in[11];
    const float* fw1  = (const float*)d_in[12];
    const float* fb1  = (const float*)d_in[13];
    const float* fw2  = (const float*)d_in[14];
    const float* fb2  = (const float*)d_in[15];
    const float* w1ns = (const float*)d_in[16];
    const float* b1ns = (const float*)d_in[17];
    const float* w2ns = (const float*)d_in[18];
    const float* b2ns = (const float*)d_in[19];
    float* out = (float*)d_out;

    float *xn,*q,*kv,*attn,*h1,*hn,*tns,*fns,*part;
    __nv_bfloat16 *xnb,*hnb,*tsb,*wqb,*w1b,*w2b;
    cudaGetSymbolAddress((void**)&xn,   g_xn);
    cudaGetSymbolAddress((void**)&q,    g_q);
    cudaGetSymbolAddress((void**)&kv,   g_kv);
    cudaGetSymbolAddress((void**)&attn, g_attn);
    cudaGetSymbolAddress((void**)&h1,   g_h1);
    cudaGetSymbolAddress((void**)&hn,   g_hn);
    cudaGetSymbolAddress((void**)&tns,  g_tns);
    cudaGetSymbolAddress((void**)&fns,  g_fns);
    cudaGetSymbolAddress((void**)&part, g_part);
    cudaGetSymbolAddress((void**)&xnb,  g_xnb);
    cudaGetSymbolAddress((void**)&hnb,  g_hnb);
    cudaGetSymbolAddress((void**)&tsb,  g_tsb);
    cudaGetSymbolAddress((void**)&wqb,  g_wqkvb);
    cudaGetSymbolAddress((void**)&w1b,  g_w1b);
    cudaGetSymbolAddress((void**)&w2b,  g_w2b);
    float* part2 = part + 2*1024*1024;

    const long aB  = (long)TOTAL*DM;
    const long qB  = (long)QLEN*DM;
    const long kvB = (long)TOTAL*2*DM;

    const int SMEMB128 = (3*128*40 + 3*128*40) * 2;   // 61440 B
    const int SMEMB64  = (3*64*40  + 3*128*40) * 2;   // 46080 B
    const int ATTSMEM  = ATT_SMEM_FLOATS * 4;
    cudaFuncSetAttribute(mma_gemmB_kernel<128>, cudaFuncAttributeMaxDynamicSharedMemorySize, SMEMB128);
    cudaFuncSetAttribute(mma_gemmB_kernel<64>,  cudaFuncAttributeMaxDynamicSharedMemorySize, SMEMB64);
    cudaFuncSetAttribute(attn_mma_kernel, cudaFuncAttributeMaxDynamicSharedMemorySize, ATTSMEM);

    static cudaStream_t s1 = nullptr, s2 = nullptr, s3 = nullptr;
    static cudaEvent_t  eB, e0, e1, e2, e2a, e3, e4, e5;
    if (s1 == nullptr) {
        cudaStreamCreateWithFlags(&s1, cudaStreamNonBlocking);
        cudaStreamCreateWithFlags(&s2, cudaStreamNonBlocking);
        cudaStreamCreateWithFlags(&s3, cudaStreamNonBlocking);
        cudaEventCreateWithFlags(&eB,  cudaEventDisableTiming);
        cudaEventCreateWithFlags(&e0,  cudaEventDisableTiming);
        cudaEventCreateWithFlags(&e1,  cudaEventDisableTiming);
        cudaEventCreateWithFlags(&e2,  cudaEventDisableTiming);
        cudaEventCreateWithFlags(&e2a, cudaEventDisableTiming);
        cudaEventCreateWithFlags(&e3,  cudaEventDisableTiming);
        cudaEventCreateWithFlags(&e4,  cudaEventDisableTiming);
        cudaEventCreateWithFlags(&e5,  cudaEventDisableTiming);
    }
    cudaStream_t s0 = 0;

    // ---- Phase 1 : rmsnorm (s0) || weight transposes (s2) ----
    cudaEventRecord(eB, s0);
    cudaStreamWaitEvent(s2, eB, 0);
    transpose_bf16_kernel<<<dim3(3*DM/32, DM/32), dim3(32,8), 0, s2>>>(wqkv, wqb, DM, 3*DM);
    cudaEventRecord(e2a, s2);
    transpose_bf16_kernel<<<dim3(FFND/32, DM/32), dim3(32,8), 0, s2>>>(fw1, w1b, DM, FFND);
    transpose_bf16_kernel<<<dim3(DM/32, FFND/32), dim3(32,8), 0, s2>>>(fw2, w2b, FFND, DM);
    cudaEventRecord(e2, s2);

    rmsnorm_kernel<<<BSZ*TOTAL, 256, 0, s0>>>(x, n1w, xn, xnb);
    cudaEventRecord(e0, s0);

    // s1: Q projection -> ns_q -> rope_q
    cudaStreamWaitEvent(s1, e0, 0);
    cudaStreamWaitEvent(s1, e2a, 0);
    mma_gemmB_kernel<64><<<dim3(DM/128, (BSZ*OUTN)/64), 256, SMEMB64, s1>>>(
        xnb + (long)(MAXS-OUTN)*DM, DM, aB, OUTN, wqb, DM, bqkv, q, DM, qB, DM, 0, 1, 0, seq, 0, nullptr);
    ns_split4_kernel<<<dim3(DM/512, NSN, 32), 128, 0, s1>>>(xn + (long)MAXS*DM, aB, DM, wnsq, part2, DM, DM, DM/32);
    ns_reduce_kernel<<<dim3(DM/256, NSN, BSZ), 256, 0, s1>>>(part2, bnsq, q + (long)OUTN*DM, qB, DM, DM, 32, 0, 1, nullptr);
    {
        int totq = BSZ*QLEN*NH*32;
        rope_kernel<<<(totq+255)/256, 256, 0, s1>>>(q, QLEN, TOTAL-QLEN, DM, totq, seq, 0);
    }
    cudaEventRecord(e1, s1);

    // s3: ns_v then ns_k
    cudaStreamWaitEvent(s3, e0, 0);
    ns_split4_kernel<<<dim3(DM/512, NSN, 32), 128, 0, s3>>>(xn + (long)MAXS*DM, aB, DM, wnsv, part, DM, DM, DM/32);
    ns_reduce_kernel<<<dim3(DM/256, NSN, BSZ), 256, 0, s3>>>(part, bnsv, kv + (long)MAXS*2*DM + DM, kvB, 2*DM, DM, 32, 0, 1, nullptr);
    ns_split4_kernel<<<dim3(DM/512, NSN, 32), 128, 0, s3>>>(xn + (long)MAXS*DM, aB, DM, wnsk, part, DM, DM, DM/32);
    ns_reduce_kernel<<<dim3(DM/256, NSN, BSZ), 256, 0, s3>>>(part, bnsk, kv + (long)MAXS*2*DM, kvB, 2*DM, DM, 32, 0, 1, nullptr);
    cudaEventRecord(e3, s3);

    // s0: KV projection, then rope_k (dead rows skipped — bit-identical)
    cudaStreamWaitEvent(s0, e2a, 0);
    mma_gemmB_kernel<128><<<dim3(2*DM/128, (BSZ*MAXS)/128), 256, SMEMB128, s0>>>(xnb, DM, aB, MAXS,
        wqb + (long)DM*DM, DM, bqkv + DM, kv, 2*DM, kvB, DM, 0, 1, 0, seq, 1, nullptr);
    cudaStreamWaitEvent(s0, e3, 0);
    {
        int totk = BSZ*TOTAL*NH*32;
        rope_kernel<<<(totk+255)/256, 256, 0, s0>>>(kv, TOTAL, 0, 2*DM, totk, seq, 1);
    }

    cudaStreamWaitEvent(s0, e1, 0);
    attn_mma_kernel<<<dim3((QLEN+63)/64, NH, BSZ), 256, ATTSMEM, s0>>>(q, kv, attn, seq);

    add_rmsnorm_kernel<<<BSZ*QLEN, 256, 0, s0>>>(x, n2w);
    cudaEventRecord(e4, s0);

    // ---- Phase 2 ----
    cudaStreamWaitEvent(s1, e4, 0);
    ns_split4_kernel<<<dim3(FFND/512, NSN, 16), 128, 0, s1>>>(hn + (long)OUTN*DM, qB, DM, w1ns, part, DM, FFND, DM/16);
    ns_reduce_kernel<<<dim3(FFND/256, NSN, BSZ), 256, 0, s1>>>(part, b1ns, tns, (long)NSN*FFND, FFND, FFND, 16, 1, 0, nullptr);
    ns_split4_kernel<<<dim3(DM/512, NSN, 32), 128, 0, s1>>>(tns, (long)NSN*FFND, FFND, w2ns, part, FFND, DM, FFND/32);
    ns_reduce_kernel<<<dim3(DM/256, NSN, BSZ), 256, 0, s1>>>(part, b2ns,
        out + (long)OUTN*DM, qB, DM, DM, 32, 0, 0, h1 + (long)OUTN*DM);
    tail_kernel<<<1, BSZ, 0, s1>>>(out, seq, out_size);   // overlaps FFN2 on s0
    cudaEventRecord(e5, s1);

    cudaStreamWaitEvent(s0, e2, 0);
    mma_gemmB_kernel<128><<<dim3(FFND/128, (BSZ*OUTN)/128), 256, SMEMB128, s0>>>(hnb, DM, qB, OUTN,
        w1b, DM, fb1, tsb, FFND, (long)OUTN*FFND, DM, 1, 0, 1, seq, 0, nullptr);
    mma_gemmB_kernel<64><<<dim3(DM/128, (BSZ*OUTN)/64), 256, SMEMB64, s0>>>(tsb, FFND, (long)OUTN*FFND, OUTN,
        w2b, FFND, fb2, out, DM, qB, FFND, 0, 0, 0, seq, 0, h1);

    // final join (required for graph capture; cheap empty node)
    cudaStreamWaitEvent(s0, e5, 0);
}